// round 2
// baseline (speedup 1.0000x reference)
#include <cuda_runtime.h>
#include <math.h>

#define NB 8
#define NWAY 16
#define NBASE 8000
#define FEAT 512
#define SEM 300
#define SEMP 304
#define CAT 816
#define NROW (NB*NWAY)
#define INV_TEMP 0.04419417382415922f

// ---------------- scratch ----------------
__device__ float g_H[(size_t)NB*NBASE*SEMP];
__device__ float g_Hs[NROW*SEM];
__device__ float g_cal[NROW*SEM];
__device__ float g_qsg[NROW*SEM];
__device__ float g_partBW[NB*16*FEAT];
__device__ float g_partH[NB*16*SEM];
__device__ float g_gatevis[NB*FEAT];
__device__ float g_gatesem[NB*SEM];
__device__ float g_qtot[NROW*FEAT];
__device__ float g_Qcat[NROW*CAT];
__device__ float g_c[NROW];
__device__ float g_m[NROW];
__device__ float g_Z[NROW];
__device__ float g_Wvc[FEAT*FEAT];
__device__ float g_part[(size_t)NB*32*NWAY*FEAT];

// ---------------- NN GEMM: C = [leaky](A@B + bias) [+C] ------------------------------
// BM=BN=128, BK=8, 256 thr, 8x8 micro, double-buffered. Requires M%128==0, N>=128,
// lda/ldb/ldc %4==0, K%4==0 (so float4 loads never straddle the K edge).
__global__ void gemm_nn(const float* __restrict__ A, int lda,
                        const float* __restrict__ B, int ldb,
                        const float* __restrict__ bias,
                        float* __restrict__ C, int ldc,
                        int K, int N, int Nstore, int leaky, int accum)
{
    __shared__ __align__(16) float As[2][8][128];
    __shared__ __align__(16) float Bs[2][8][128];
    int col0 = blockIdx.x * 128; if (col0 > N - 128) col0 = N - 128;
    int row0 = blockIdx.y * 128;
    int t = threadIdx.x;
    int arow = t >> 1, akq = (t & 1) * 4;
    int bkk = t >> 5, bc4 = (t & 31) * 4;
    const float* Aptr = A + (size_t)(row0 + arow) * lda + akq;
    const float* Bptr = B + (size_t)bkk * ldb + col0 + bc4;
    int nt = (K + 7) / 8;
    float4 av, bv;
    av = (akq < K) ? *reinterpret_cast<const float4*>(Aptr) : make_float4(0,0,0,0);
    bv = (bkk < K) ? *reinterpret_cast<const float4*>(Bptr) : make_float4(0,0,0,0);
    As[0][akq+0][arow]=av.x; As[0][akq+1][arow]=av.y; As[0][akq+2][arow]=av.z; As[0][akq+3][arow]=av.w;
    Bs[0][bkk][bc4+0]=bv.x;  Bs[0][bkk][bc4+1]=bv.y;  Bs[0][bkk][bc4+2]=bv.z;  Bs[0][bkk][bc4+3]=bv.w;
    __syncthreads();
    int tx = t & 15, ty = t >> 4;
    float acc[8][8] = {};
    for (int kt = 0; kt < nt; kt++) {
        int cur = kt & 1;
        if (kt + 1 < nt) {
            int ka = (kt+1)*8 + akq;
            av = (ka < K) ? *reinterpret_cast<const float4*>(Aptr + (kt+1)*8) : make_float4(0,0,0,0);
            int kb = (kt+1)*8 + bkk;
            bv = (kb < K) ? *reinterpret_cast<const float4*>(Bptr + (size_t)(kt+1)*8*ldb) : make_float4(0,0,0,0);
        }
        #pragma unroll
        for (int kk = 0; kk < 8; kk++) {
            float4 a0 = *reinterpret_cast<const float4*>(&As[cur][kk][ty*8]);
            float4 a1 = *reinterpret_cast<const float4*>(&As[cur][kk][ty*8+4]);
            float4 b0 = *reinterpret_cast<const float4*>(&Bs[cur][kk][tx*8]);
            float4 b1 = *reinterpret_cast<const float4*>(&Bs[cur][kk][tx*8+4]);
            float a[8] = {a0.x,a0.y,a0.z,a0.w,a1.x,a1.y,a1.z,a1.w};
            float b[8] = {b0.x,b0.y,b0.z,b0.w,b1.x,b1.y,b1.z,b1.w};
            #pragma unroll
            for (int i = 0; i < 8; i++)
                #pragma unroll
                for (int j = 0; j < 8; j++) acc[i][j] += a[i]*b[j];
        }
        if (kt + 1 < nt) {
            int nx = cur ^ 1;
            As[nx][akq+0][arow]=av.x; As[nx][akq+1][arow]=av.y; As[nx][akq+2][arow]=av.z; As[nx][akq+3][arow]=av.w;
            Bs[nx][bkk][bc4+0]=bv.x;  Bs[nx][bkk][bc4+1]=bv.y;  Bs[nx][bkk][bc4+2]=bv.z;  Bs[nx][bkk][bc4+3]=bv.w;
        }
        __syncthreads();
    }
    #pragma unroll
    for (int i = 0; i < 8; i++) {
        int row = row0 + ty*8 + i;
        #pragma unroll
        for (int j = 0; j < 8; j++) {
            int col = col0 + tx*8 + j;
            if (col < Nstore) {
                float v = acc[i][j];
                if (bias) v += bias[col];
                if (leaky) v = (v >= 0.f) ? v : 0.1f*v;
                float* cp = C + (size_t)row*ldc + col;
                if (accum) v += *cp;
                *cp = v;
            }
        }
    }
}

// ---------------- TN GEMM: C = (A @ B^T) [* gate_bcast]  (M fixed = 128) -------------
__global__ void gemm_tn(const float* __restrict__ A, int lda,
                        const float* __restrict__ B, int ldb,
                        float* __restrict__ C, int ldc,
                        int K, int N, int Nstore,
                        const float* __restrict__ gate, int gstride)
{
    __shared__ __align__(16) float As[2][8][128];
    __shared__ __align__(16) float Bs[2][8][128];
    int col0 = blockIdx.x * 128; if (col0 > N - 128) col0 = N - 128;
    int t = threadIdx.x;
    int arow = t >> 1, akq = (t & 1) * 4;   // same pattern for A and B (both K-major)
    const float* Aptr = A + (size_t)arow * lda + akq;
    const float* Bptr = B + (size_t)(col0 + arow) * ldb + akq;
    int nt = (K + 7) / 8;
    float4 av, bv;
    av = (akq < K) ? *reinterpret_cast<const float4*>(Aptr) : make_float4(0,0,0,0);
    bv = (akq < K) ? *reinterpret_cast<const float4*>(Bptr) : make_float4(0,0,0,0);
    As[0][akq+0][arow]=av.x; As[0][akq+1][arow]=av.y; As[0][akq+2][arow]=av.z; As[0][akq+3][arow]=av.w;
    Bs[0][akq+0][arow]=bv.x; Bs[0][akq+1][arow]=bv.y; Bs[0][akq+2][arow]=bv.z; Bs[0][akq+3][arow]=bv.w;
    __syncthreads();
    int tx = t & 15, ty = t >> 4;
    float acc[8][8] = {};
    for (int kt = 0; kt < nt; kt++) {
        int cur = kt & 1;
        if (kt + 1 < nt) {
            int k = (kt+1)*8 + akq;
            av = (k < K) ? *reinterpret_cast<const float4*>(Aptr + (kt+1)*8) : make_float4(0,0,0,0);
            bv = (k < K) ? *reinterpret_cast<const float4*>(Bptr + (kt+1)*8) : make_float4(0,0,0,0);
        }
        #pragma unroll
        for (int kk = 0; kk < 8; kk++) {
            float4 a0 = *reinterpret_cast<const float4*>(&As[cur][kk][ty*8]);
            float4 a1 = *reinterpret_cast<const float4*>(&As[cur][kk][ty*8+4]);
            float4 b0 = *reinterpret_cast<const float4*>(&Bs[cur][kk][tx*8]);
            float4 b1 = *reinterpret_cast<const float4*>(&Bs[cur][kk][tx*8+4]);
            float a[8] = {a0.x,a0.y,a0.z,a0.w,a1.x,a1.y,a1.z,a1.w};
            float b[8] = {b0.x,b0.y,b0.z,b0.w,b1.x,b1.y,b1.z,b1.w};
            #pragma unroll
            for (int i = 0; i < 8; i++)
                #pragma unroll
                for (int j = 0; j < 8; j++) acc[i][j] += a[i]*b[j];
        }
        if (kt + 1 < nt) {
            int nx = cur ^ 1;
            As[nx][akq+0][arow]=av.x; As[nx][akq+1][arow]=av.y; As[nx][akq+2][arow]=av.z; As[nx][akq+3][arow]=av.w;
            Bs[nx][akq+0][arow]=bv.x; Bs[nx][akq+1][arow]=bv.y; Bs[nx][akq+2][arow]=bv.z; Bs[nx][akq+3][arow]=bv.w;
        }
        __syncthreads();
    }
    #pragma unroll
    for (int i = 0; i < 8; i++) {
        int row = ty*8 + i;
        #pragma unroll
        for (int j = 0; j < 8; j++) {
            int col = col0 + tx*8 + j;
            if (col < Nstore) {
                float v = acc[i][j];
                if (gate) v *= gate[(row >> 4) * gstride + col];
                C[(size_t)row*ldc + col] = v;
            }
        }
    }
}

// ---------------- K1: partial column sums of base_weights ----------------------------
__global__ void k1_partBW(const float* __restrict__ bw) {
    int b = blockIdx.y, s = blockIdx.x, t = threadIdx.x;
    int n0 = s * 500;
    const float* base = bw + ((size_t)(b*NBASE + n0))*FEAT;
    float a0 = 0.f, a1 = 0.f;
    for (int n = 0; n < 500; n++) {
        const float* r = base + (size_t)n*FEAT;
        a0 += r[t]; a1 += r[t+256];
    }
    g_partBW[(b*16+s)*FEAT + t]       = a0;
    g_partBW[(b*16+s)*FEAT + t + 256] = a1;
}

// ---------------- pad zeroing (H cols 300..303, Qcat cols 812..815) ------------------
__global__ void kpad() {
    int i = blockIdx.x*blockDim.x + threadIdx.x;
    if (i < NB*NBASE*4) {
        int row = i >> 2;
        g_H[(size_t)row*SEMP + 300 + (i & 3)] = 0.f;
    }
    if (i < NROW*4) g_Qcat[(i >> 2)*CAT + 812 + (i & 3)] = 0.f;
}

// ---------------- K2b: partial column sums of H --------------------------------------
__global__ void k2b_partH() {
    int b = blockIdx.y, s = blockIdx.x, t = threadIdx.x;
    if (t >= SEM) return;
    int n0 = s * 500;
    const float* base = g_H + ((size_t)(b*NBASE + n0))*SEMP;
    float a = 0.f;
    for (int n = 0; n < 500; n++) a += base[(size_t)n*SEMP + t];
    g_partH[(b*16+s)*SEM + t] = a;
}

// ---------------- K4: means -> fusion gates ------------------------------------------
__global__ void k4_gates(const float* __restrict__ W2, const float* __restrict__ B2,
                         const float* __restrict__ Vw, const float* __restrict__ Vb,
                         const float* __restrict__ Sw, const float* __restrict__ Sb) {
    __shared__ float s_avg[FEAT + SEM];
    __shared__ float s_mh[SEM];
    int b = blockIdx.x, t = threadIdx.x;
    if (t < FEAT) {
        float a = 0.f;
        for (int s = 0; s < 16; s++) a += g_partBW[(b*16+s)*FEAT + t];
        s_avg[t] = a * (1.f/NBASE);
    }
    if (t < SEM) {
        float a = 0.f;
        for (int s = 0; s < 16; s++) a += g_partH[(b*16+s)*SEM + t];
        s_mh[t] = a * (1.f/NBASE);
    }
    __syncthreads();
    if (t < SEM) {
        float c = B2[t];
        #pragma unroll 8
        for (int k = 0; k < SEM; k++) c += s_mh[k]*W2[(size_t)k*SEM + t];
        s_avg[FEAT + t] = c;
    }
    __syncthreads();
    {
        float g = Vb[t];
        #pragma unroll 8
        for (int k = 0; k < FEAT+SEM; k++) g += s_avg[k]*Vw[(size_t)k*FEAT + t];
        g_gatevis[b*FEAT + t] = 1.f + 1.f/(1.f + expf(-g));
    }
    if (t < SEM) {
        float g = Sb[t];
        #pragma unroll 8
        for (int k = 0; k < FEAT+SEM; k++) g += s_avg[k]*Sw[(size_t)k*SEM + t];
        g_gatesem[b*SEM + t] = 1.f + 1.f/(1.f + expf(-g));
    }
}

// ---------------- K5c: g_c = qsg . b2 ------------------------------------------------
__global__ void k5c_c(const float* __restrict__ B2) {
    int row = blockIdx.x, lane = threadIdx.x;
    float acc = 0.f;
    for (int s = lane; s < SEM; s += 32) acc += g_qsg[row*SEM + s]*B2[s];
    for (int off = 16; off; off >>= 1) acc += __shfl_xor_sync(0xffffffffu, acc, off);
    if (lane == 0) g_c[row] = acc;
}

// ---------------- K6: scores = Qcat @ [BW | H]^T / TEMP ------------------------------
__global__ void k6_score(const float* __restrict__ bw, float* __restrict__ attn) {
    __shared__ __align__(16) float Qs[16][16];
    __shared__ __align__(16) float Xst[16][132];
    int b = blockIdx.y, ch = blockIdx.x;
    int n0 = ch*128;
    int nvalid = NBASE - n0; if (nvalid > 128) nvalid = 128;
    int t = threadIdx.x, lane = t & 31, warp = t >> 5;
    float acc0[4] = {0,0,0,0}, acc1[4] = {0,0,0,0};
    for (int kt = 0; kt < 51; kt++) {
        { int w = t >> 4, k = t & 15;
          Qs[w][k] = g_Qcat[(size_t)(b*NWAY + w)*CAT + kt*16 + k]; }
        #pragma unroll
        for (int i = 0; i < 2; i++) {
            int v = t + 256*i;
            int kg = v & 3, n = v >> 2;
            int kk = kt*16 + kg*4;
            float4 f = make_float4(0.f,0.f,0.f,0.f);
            if (n < nvalid) {
                if (kk < FEAT)
                    f = *reinterpret_cast<const float4*>(bw + (size_t)(b*NBASE + n0 + n)*FEAT + kk);
                else
                    f = *reinterpret_cast<const float4*>(g_H + (size_t)(b*NBASE + n0 + n)*SEMP + (kk - FEAT));
            }
            Xst[kg*4+0][n] = f.x; Xst[kg*4+1][n] = f.y; Xst[kg*4+2][n] = f.z; Xst[kg*4+3][n] = f.w;
        }
        __syncthreads();
        #pragma unroll
        for (int k = 0; k < 16; k++) {
            float q0 = Qs[warp][k];
            float q1 = Qs[warp+8][k];
            float4 x = *reinterpret_cast<const float4*>(&Xst[k][lane*4]);
            acc0[0] += q0*x.x; acc0[1] += q0*x.y; acc0[2] += q0*x.z; acc0[3] += q0*x.w;
            acc1[0] += q1*x.x; acc1[1] += q1*x.y; acc1[2] += q1*x.z; acc1[3] += q1*x.w;
        }
        __syncthreads();
    }
    float c0 = g_c[b*NWAY + warp], c1 = g_c[b*NWAY + warp + 8];
    #pragma unroll
    for (int j = 0; j < 4; j++) {
        int n = lane*4 + j;
        if (n < nvalid) {
            attn[(size_t)(b*NWAY + warp    )*NBASE + n0 + n] = (acc0[j] + c0) * INV_TEMP;
            attn[(size_t)(b*NWAY + warp + 8)*NBASE + n0 + n] = (acc1[j] + c1) * INV_TEMP;
        }
    }
}

// ---------------- K7: softmax stats --------------------------------------------------
__global__ void k7_stats(const float* __restrict__ attn) {
    __shared__ float red[256];
    int idx = blockIdx.x, t = threadIdx.x;
    const float* row = attn + (size_t)idx*NBASE;
    float m = -1e30f;
    for (int n = t; n < NBASE; n += 256) m = fmaxf(m, row[n]);
    red[t] = m; __syncthreads();
    for (int s = 128; s; s >>= 1) { if (t < s) red[t] = fmaxf(red[t], red[t+s]); __syncthreads(); }
    m = red[0]; __syncthreads();
    float z = 0.f;
    for (int n = t; n < NBASE; n += 256) z += expf(row[n] - m);
    red[t] = z; __syncthreads();
    for (int s = 128; s; s >>= 1) { if (t < s) red[t] += red[t+s]; __syncthreads(); }
    if (t == 0) { g_m[idx] = m; g_Z[idx] = red[0]; }
}

// ---------------- K8: partial attn @ base_weights ------------------------------------
__global__ void k8_part(const float* __restrict__ bw, const float* __restrict__ attn) {
    __shared__ float p[NWAY*250];
    int b = blockIdx.y, c = blockIdx.x, t = threadIdx.x;
    int n0 = c*250;
    for (int v = t; v < NWAY*250; v += 256) {
        int w = v/250, n = v%250;
        float s = attn[(size_t)(b*NWAY+w)*NBASE + n0 + n];
        p[w*250+n] = expf(s - g_m[b*NWAY+w]);
    }
    __syncthreads();
    float a0[NWAY], a1[NWAY];
    #pragma unroll
    for (int w = 0; w < NWAY; w++) { a0[w] = 0.f; a1[w] = 0.f; }
    for (int n = 0; n < 250; n++) {
        const float* r = bw + (size_t)(b*NBASE + n0 + n)*FEAT;
        float x0 = r[t], x1 = r[t+256];
        #pragma unroll
        for (int w = 0; w < NWAY; w++) {
            float pw = p[w*250+n];
            a0[w] += pw*x0; a1[w] += pw*x1;
        }
    }
    for (int w = 0; w < NWAY; w++) {
        size_t o = (size_t)((b*32 + c)*NWAY + w)*FEAT;
        g_part[o + t]       = a0[w];
        g_part[o + t + 256] = a1[w];
    }
}

// ---------------- K9: reduce partials, @Wvc, +residual -------------------------------
__global__ void k9_out(const float* __restrict__ sf, float* __restrict__ out) {
    __shared__ float s_s[FEAT];
    int idx = blockIdx.x, t = threadIdx.x;
    int b = idx >> 4, w = idx & 15;
    float acc = 0.f;
    for (int c = 0; c < 32; c++) acc += g_part[(size_t)((b*32+c)*NWAY + w)*FEAT + t];
    s_s[t] = acc / g_Z[idx];
    __syncthreads();
    float v = sf[(size_t)idx*FEAT + t];
    #pragma unroll 4
    for (int d = 0; d < FEAT; d++) v += s_s[d]*g_Wvc[(size_t)d*FEAT + t];
    out[(size_t)idx*FEAT + t] = v;
}

// ---------------- launch --------------------------------------------------------------
extern "C" void kernel_launch(void* const* d_in, const int* in_sizes, int n_in,
                              void* d_out, int out_size) {
    const float* sf  = (const float*)d_in[0];
    const float* bw  = (const float*)d_in[1];
    const float* ss  = (const float*)d_in[2];
    const float* bs  = (const float*)d_in[3];
    const float* w1  = (const float*)d_in[4];
    const float* b1  = (const float*)d_in[5];
    const float* w2  = (const float*)d_in[6];
    const float* b2  = (const float*)d_in[7];
    const float* vw  = (const float*)d_in[8];
    const float* vb  = (const float*)d_in[9];
    const float* swf = (const float*)d_in[10];
    const float* sb  = (const float*)d_in[11];
    const float* wq  = (const float*)d_in[12];
    const float* wk  = (const float*)d_in[13];
    const float* wv  = (const float*)d_in[14];
    const float* wqs = (const float*)d_in[15];
    const float* wks = (const float*)d_in[16];
    const float* fc  = (const float*)d_in[17];
    float* out  = (float*)d_out;
    float* attn = out + (size_t)NROW*FEAT;

    float *pH, *pHs, *pcal, *pqtot, *pqsg, *pQcat, *pWvc, *pgv, *pgs;
    cudaGetSymbolAddress((void**)&pH,    g_H);
    cudaGetSymbolAddress((void**)&pHs,   g_Hs);
    cudaGetSymbolAddress((void**)&pcal,  g_cal);
    cudaGetSymbolAddress((void**)&pqtot, g_qtot);
    cudaGetSymbolAddress((void**)&pqsg,  g_qsg);
    cudaGetSymbolAddress((void**)&pQcat, g_Qcat);
    cudaGetSymbolAddress((void**)&pWvc,  g_Wvc);
    cudaGetSymbolAddress((void**)&pgv,   g_gatevis);
    cudaGetSymbolAddress((void**)&pgs,   g_gatesem);

    // base means
    k1_partBW<<<dim3(16, NB), 256>>>(bw);
    // H = leaky(base_seman @ w1 + b1)   (the big GEMM)
    gemm_nn<<<dim3(3, 500), 256>>>(bs, SEM, w1, SEM, b1, pH, SEMP, SEM, SEM, SEM, 1, 0);
    kpad<<<1000, 256>>>();
    k2b_partH<<<dim3(16, NB), 320>>>();
    // support path: Hs -> cal -> qtot
    gemm_nn<<<dim3(3, 1), 256>>>(ss,  SEM, w1, SEM, b1, pHs,  SEM, SEM, SEM, SEM, 1, 0);
    gemm_nn<<<dim3(3, 1), 256>>>(pHs, SEM, w2, SEM, b2, pcal, SEM, SEM, SEM, SEM, 0, 0);
    gemm_nn<<<dim3(4, 1), 256>>>(sf,   FEAT, wq,  FEAT, nullptr, pqtot, FEAT, FEAT, FEAT, FEAT, 0, 0);
    gemm_nn<<<dim3(4, 1), 256>>>(pcal, SEM,  wqs, FEAT, nullptr, pqtot, FEAT, SEM,  FEAT, FEAT, 0, 1);
    // gates + Wvc
    k4_gates<<<NB, 512>>>(w2, b2, vw, vb, swf, sb);
    gemm_nn<<<dim3(4, 4), 256>>>(wv, FEAT, fc, FEAT, nullptr, pWvc, FEAT, FEAT, FEAT, FEAT, 0, 0);
    // fold keys into the query side
    gemm_tn<<<dim3(4, 1), 256>>>(pqtot, FEAT, wk,  FEAT, pQcat,        CAT, FEAT, FEAT, FEAT, pgv, FEAT);
    gemm_tn<<<dim3(3, 1), 256>>>(pqtot, FEAT, wks, FEAT, pqsg,         SEM, FEAT, SEM,  SEM,  pgs, SEM);
    gemm_tn<<<dim3(3, 1), 256>>>(pqsg,  SEM,  w2,  SEM,  pQcat + FEAT, CAT, SEM,  SEM,  SEM,  nullptr, 0);
    k5c_c<<<NROW, 32>>>(b2);
    // scores, softmax, output
    k6_score<<<dim3(63, NB), 256>>>(bw, attn);
    k7_stats<<<NROW, 256>>>(attn);
    k8_part<<<dim3(32, NB), 256>>>(bw, attn);
    k9_out<<<NROW, 512>>>(sf, out);
}

// round 4
// speedup vs baseline: 1.1163x; 1.1163x over previous
#include <cuda_runtime.h>
#include <cstdint>
#include <math.h>

#define NB 8
#define NWAY 16
#define NBASE 8000
#define FEAT 512
#define SEM 300
#define SEMP 304
#define CAT 816
#define NROW (NB*NWAY)
#define INV_TEMP 0.04419417382415922f

// ---------------- scratch ----------------
__device__ float g_H[(size_t)NB*NBASE*SEMP];
__device__ float g_partBW[NB*16*FEAT];
__device__ float g_partH[NB*16*SEM];
__device__ float g_gatevis[NB*FEAT];
__device__ float g_gatesem[NB*SEM];
__device__ float g_qtot[NROW*FEAT];
__device__ float g_Qcat[NROW*CAT];
__device__ float g_c[NROW];
__device__ float g_m[NROW];
__device__ float g_Z[NROW];
__device__ float g_Wvc[FEAT*FEAT];
__device__ float g_part[(size_t)NB*32*NWAY*FEAT];

// ---------------- packed f32x2 helpers ----------------
__device__ __forceinline__ unsigned long long f2fma(unsigned long long a, unsigned long long b, unsigned long long c) {
    unsigned long long d;
    asm("fma.rn.f32x2 %0, %1, %2, %3;" : "=l"(d) : "l"(a), "l"(b), "l"(c));
    return d;
}
__device__ __forceinline__ unsigned long long f2pk(float x, float y) {
    unsigned long long r;
    asm("mov.b64 %0, {%1, %2};" : "=l"(r) : "f"(x), "f"(y));
    return r;
}
__device__ __forceinline__ void f2up(unsigned long long v, float& x, float& y) {
    asm("mov.b64 {%0, %1}, %2;" : "=f"(x), "=f"(y) : "l"(v));
}

// ============ K2: H = leaky(base_seman @ w1 + b1), packed-f32x2 GEMM ============
// 64000x300 @ 300x300, BM=128, BN=128 (col0 in {0,128,176}), BK=8, 256 thr, 8x8 micro.
__global__ __launch_bounds__(256) void k2_pk(const float* __restrict__ A,
                                             const float* __restrict__ W,
                                             const float* __restrict__ bias) {
    __shared__ unsigned long long As64[2][8][128];   // (a,a) duplicated pairs
    __shared__ float Bs[2][8][128];
    const int colTab[3] = {0, 128, 176};
    int col0 = colTab[blockIdx.x];
    int row0 = blockIdx.y * 128;
    int t = threadIdx.x;
    int arow = t >> 1, akq = (t & 1) * 4;
    int bkk = t >> 5, bn4 = (t & 31) * 4;
    bool bnv = (col0 + bn4) < SEM;                   // SEM%4==0 -> full-float4 validity
    const float* Ap = A + (size_t)(row0 + arow) * SEM + akq;
    const float* Wp = W + (size_t)bkk * SEM + col0 + bn4;
    const int nt = 38;                               // ceil(300/8)
    float4 av, bv;
    av = (akq < SEM) ? *reinterpret_cast<const float4*>(Ap) : make_float4(0,0,0,0);
    bv = (bnv && bkk < SEM) ? *reinterpret_cast<const float4*>(Wp) : make_float4(0,0,0,0);
    As64[0][akq+0][arow] = f2pk(av.x, av.x);
    As64[0][akq+1][arow] = f2pk(av.y, av.y);
    As64[0][akq+2][arow] = f2pk(av.z, av.z);
    As64[0][akq+3][arow] = f2pk(av.w, av.w);
    Bs[0][bkk][bn4+0] = bv.x; Bs[0][bkk][bn4+1] = bv.y;
    Bs[0][bkk][bn4+2] = bv.z; Bs[0][bkk][bn4+3] = bv.w;
    __syncthreads();
    int tx = t & 15, ty = t >> 4;
    unsigned long long acc[8][4];
    #pragma unroll
    for (int i = 0; i < 8; i++)
        #pragma unroll
        for (int j = 0; j < 4; j++) acc[i][j] = 0ULL;
    for (int kt = 0; kt < nt; kt++) {
        int cur = kt & 1;
        if (kt + 1 < nt) {
            int ka = (kt+1)*8 + akq;
            av = (ka < SEM) ? *reinterpret_cast<const float4*>(Ap + (kt+1)*8) : make_float4(0,0,0,0);
            int kb = (kt+1)*8 + bkk;
            bv = (bnv && kb < SEM) ? *reinterpret_cast<const float4*>(Wp + (size_t)(kt+1)*8*SEM) : make_float4(0,0,0,0);
        }
        #pragma unroll
        for (int kk = 0; kk < 8; kk++) {
            unsigned long long a[8];
            #pragma unroll
            for (int i = 0; i < 8; i++) a[i] = As64[cur][kk][ty*8 + i];
            const unsigned long long* bp = reinterpret_cast<const unsigned long long*>(&Bs[cur][kk][tx*8]);
            unsigned long long b0 = bp[0], b1 = bp[1], b2 = bp[2], b3 = bp[3];
            #pragma unroll
            for (int i = 0; i < 8; i++) {
                acc[i][0] = f2fma(a[i], b0, acc[i][0]);
                acc[i][1] = f2fma(a[i], b1, acc[i][1]);
                acc[i][2] = f2fma(a[i], b2, acc[i][2]);
                acc[i][3] = f2fma(a[i], b3, acc[i][3]);
            }
        }
        if (kt + 1 < nt) {
            int nx = cur ^ 1;
            As64[nx][akq+0][arow] = f2pk(av.x, av.x);
            As64[nx][akq+1][arow] = f2pk(av.y, av.y);
            As64[nx][akq+2][arow] = f2pk(av.z, av.z);
            As64[nx][akq+3][arow] = f2pk(av.w, av.w);
            Bs[nx][bkk][bn4+0] = bv.x; Bs[nx][bkk][bn4+1] = bv.y;
            Bs[nx][bkk][bn4+2] = bv.z; Bs[nx][bkk][bn4+3] = bv.w;
        }
        __syncthreads();
    }
    // epilogue: bias + leaky, zero pad cols, vector stores
    #pragma unroll
    for (int i = 0; i < 8; i++) {
        int row = row0 + ty*8 + i;
        float c[8];
        f2up(acc[i][0], c[0], c[1]);
        f2up(acc[i][1], c[2], c[3]);
        f2up(acc[i][2], c[4], c[5]);
        f2up(acc[i][3], c[6], c[7]);
        #pragma unroll
        for (int cc = 0; cc < 8; cc++) {
            int col = col0 + tx*8 + cc;
            float v = 0.f;
            if (col < SEM) {
                float x = c[cc] + bias[col];
                v = (x >= 0.f) ? x : 0.1f*x;
            }
            c[cc] = v;
        }
        float* dst = g_H + (size_t)row*SEMP + col0 + tx*8;
        *reinterpret_cast<float4*>(dst)     = make_float4(c[0], c[1], c[2], c[3]);
        *reinterpret_cast<float4*>(dst + 4) = make_float4(c[4], c[5], c[6], c[7]);
    }
}

// ---------------- K1: partial column sums of base_weights ----------------------------
__global__ void k1_partBW(const float* __restrict__ bw) {
    int b = blockIdx.y, s = blockIdx.x, t = threadIdx.x;
    int n0 = s * 500;
    const float* base = bw + ((size_t)(b*NBASE + n0))*FEAT;
    float a0 = 0.f, a1 = 0.f, a2 = 0.f, a3 = 0.f;
    #pragma unroll 2
    for (int n = 0; n < 500; n += 2) {
        const float* r0 = base + (size_t)n*FEAT;
        const float* r1 = r0 + FEAT;
        a0 += r0[t]; a1 += r0[t+256];
        a2 += r1[t]; a3 += r1[t+256];
    }
    g_partBW[(b*16+s)*FEAT + t]       = a0 + a2;
    g_partBW[(b*16+s)*FEAT + t + 256] = a1 + a3;
}

// ---------------- K2b: partial column sums of H --------------------------------------
__global__ void k2b_partH() {
    int b = blockIdx.y, s = blockIdx.x, t = threadIdx.x;
    if (t >= SEM) return;
    int n0 = s * 500;
    const float* base = g_H + ((size_t)(b*NBASE + n0))*SEMP;
    float a0 = 0.f, a1 = 0.f;
    #pragma unroll 2
    for (int n = 0; n < 500; n += 2) {
        a0 += base[(size_t)n*SEMP + t];
        a1 += base[(size_t)(n+1)*SEMP + t];
    }
    g_partH[(b*16+s)*SEM + t] = a0 + a1;
}

// ---------------- K3: support semantic calibration + q_tot (ILP version) -------------
__global__ __launch_bounds__(512) void k3_qtot(
        const float* __restrict__ sf, const float* __restrict__ ss,
        const float* __restrict__ W1, const float* __restrict__ B1,
        const float* __restrict__ W2, const float* __restrict__ B2,
        const float* __restrict__ Wq, const float* __restrict__ Wqs) {
    __shared__ float s_ss[SEM], s_hid[SEM], s_cal[SEM], s_sf[FEAT];
    int idx = blockIdx.x, t = threadIdx.x;
    if (t < SEM) s_ss[t] = ss[(size_t)idx*SEM + t];
    s_sf[t] = sf[(size_t)idx*FEAT + t];
    __syncthreads();
    if (t < SEM) {
        float a0=0.f, a1=0.f, a2=0.f, a3=0.f;
        #pragma unroll 4
        for (int k = 0; k < SEM; k += 4) {
            a0 += s_ss[k  ]*W1[(size_t)(k  )*SEM + t];
            a1 += s_ss[k+1]*W1[(size_t)(k+1)*SEM + t];
            a2 += s_ss[k+2]*W1[(size_t)(k+2)*SEM + t];
            a3 += s_ss[k+3]*W1[(size_t)(k+3)*SEM + t];
        }
        float h = B1[t] + ((a0+a1)+(a2+a3));
        s_hid[t] = (h >= 0.f) ? h : 0.1f*h;
    }
    __syncthreads();
    if (t < SEM) {
        float a0=0.f, a1=0.f, a2=0.f, a3=0.f;
        #pragma unroll 4
        for (int k = 0; k < SEM; k += 4) {
            a0 += s_hid[k  ]*W2[(size_t)(k  )*SEM + t];
            a1 += s_hid[k+1]*W2[(size_t)(k+1)*SEM + t];
            a2 += s_hid[k+2]*W2[(size_t)(k+2)*SEM + t];
            a3 += s_hid[k+3]*W2[(size_t)(k+3)*SEM + t];
        }
        s_cal[t] = B2[t] + ((a0+a1)+(a2+a3));
    }
    __syncthreads();
    float q0=0.f, q1=0.f, q2=0.f, q3=0.f;
    #pragma unroll 4
    for (int k = 0; k < FEAT; k += 4) {
        q0 += s_sf[k  ]*Wq[(size_t)(k  )*FEAT + t];
        q1 += s_sf[k+1]*Wq[(size_t)(k+1)*FEAT + t];
        q2 += s_sf[k+2]*Wq[(size_t)(k+2)*FEAT + t];
        q3 += s_sf[k+3]*Wq[(size_t)(k+3)*FEAT + t];
    }
    #pragma unroll 4
    for (int k = 0; k < SEM; k += 4) {
        q0 += s_cal[k  ]*Wqs[(size_t)(k  )*FEAT + t];
        q1 += s_cal[k+1]*Wqs[(size_t)(k+1)*FEAT + t];
        q2 += s_cal[k+2]*Wqs[(size_t)(k+2)*FEAT + t];
        q3 += s_cal[k+3]*Wqs[(size_t)(k+3)*FEAT + t];
    }
    g_qtot[(size_t)idx*FEAT + t] = (q0+q1)+(q2+q3);
}

// ---------------- K4: means -> fusion gates ------------------------------------------
__global__ void k4_gates(const float* __restrict__ W2, const float* __restrict__ B2,
                         const float* __restrict__ Vw, const float* __restrict__ Vb,
                         const float* __restrict__ Sw, const float* __restrict__ Sb) {
    __shared__ float s_avg[FEAT + SEM];
    __shared__ float s_mh[SEM];
    int b = blockIdx.x, t = threadIdx.x;
    if (t < FEAT) {
        float a = 0.f;
        for (int s = 0; s < 16; s++) a += g_partBW[(b*16+s)*FEAT + t];
        s_avg[t] = a * (1.f/NBASE);
    }
    if (t < SEM) {
        float a = 0.f;
        for (int s = 0; s < 16; s++) a += g_partH[(b*16+s)*SEM + t];
        s_mh[t] = a * (1.f/NBASE);
    }
    __syncthreads();
    if (t < SEM) {
        float a0=0.f, a1=0.f, a2=0.f, a3=0.f;
        #pragma unroll 4
        for (int k = 0; k < SEM; k += 4) {
            a0 += s_mh[k  ]*W2[(size_t)(k  )*SEM + t];
            a1 += s_mh[k+1]*W2[(size_t)(k+1)*SEM + t];
            a2 += s_mh[k+2]*W2[(size_t)(k+2)*SEM + t];
            a3 += s_mh[k+3]*W2[(size_t)(k+3)*SEM + t];
        }
        s_avg[FEAT + t] = B2[t] + ((a0+a1)+(a2+a3));
    }
    __syncthreads();
    {
        float a0=0.f, a1=0.f, a2=0.f, a3=0.f;
        #pragma unroll 4
        for (int k = 0; k < FEAT+SEM-3; k += 4) {
            a0 += s_avg[k  ]*Vw[(size_t)(k  )*FEAT + t];
            a1 += s_avg[k+1]*Vw[(size_t)(k+1)*FEAT + t];
            a2 += s_avg[k+2]*Vw[(size_t)(k+2)*FEAT + t];
            a3 += s_avg[k+3]*Vw[(size_t)(k+3)*FEAT + t];
        }
        float g = Vb[t] + ((a0+a1)+(a2+a3));
        g_gatevis[b*FEAT + t] = 1.f + 1.f/(1.f + expf(-g));
    }
    if (t < SEM) {
        float a0=0.f, a1=0.f, a2=0.f, a3=0.f;
        #pragma unroll 4
        for (int k = 0; k < FEAT+SEM-3; k += 4) {
            a0 += s_avg[k  ]*Sw[(size_t)(k  )*SEM + t];
            a1 += s_avg[k+1]*Sw[(size_t)(k+1)*SEM + t];
            a2 += s_avg[k+2]*Sw[(size_t)(k+2)*SEM + t];
            a3 += s_avg[k+3]*Sw[(size_t)(k+3)*SEM + t];
        }
        float g = Sb[t] + ((a0+a1)+(a2+a3));
        g_gatesem[b*SEM + t] = 1.f + 1.f/(1.f + expf(-g));
    }
}

// ---------------- K4b: Wvc = w_vs @ fc_w ---------------------------------------------
__global__ void k4b_wvc(const float* __restrict__ Wv, const float* __restrict__ Fc) {
    __shared__ float s_row[FEAT];
    int r = blockIdx.x, t = threadIdx.x;
    s_row[t] = Wv[(size_t)r*FEAT + t];
    __syncthreads();
    float a0=0.f, a1=0.f, a2=0.f, a3=0.f;
    #pragma unroll 4
    for (int k = 0; k < FEAT; k += 4) {
        a0 += s_row[k  ]*Fc[(size_t)(k  )*FEAT + t];
        a1 += s_row[k+1]*Fc[(size_t)(k+1)*FEAT + t];
        a2 += s_row[k+2]*Fc[(size_t)(k+2)*FEAT + t];
        a3 += s_row[k+3]*Fc[(size_t)(k+3)*FEAT + t];
    }
    g_Wvc[(size_t)r*FEAT + t] = (a0+a1)+(a2+a3);
}

// ---------------- K5: fold W_k / gates / W2 into the query side ----------------------
__global__ void k5_qcat(const float* __restrict__ Wk, const float* __restrict__ Wks,
                        const float* __restrict__ W2, const float* __restrict__ B2) {
    __shared__ float s_q[FEAT];
    __shared__ float s_qsg[SEM];
    int idx = blockIdx.x, b = idx >> 4;
    int t = threadIdx.x, lane = t & 31, warp = t >> 5;
    s_q[t] = g_qtot[(size_t)idx*FEAT + t];
    __syncthreads();
    for (int i = 0; i < 32; i++) {
        int d = warp + i*16;
        float acc = 0.f;
        for (int o = lane; o < FEAT; o += 32) acc += s_q[o]*Wk[(size_t)d*FEAT + o];
        for (int off = 16; off; off >>= 1) acc += __shfl_xor_sync(0xffffffffu, acc, off);
        if (lane == 0) g_Qcat[(size_t)idx*CAT + d] = acc * g_gatevis[b*FEAT + d];
    }
    for (int i = 0; i < 19; i++) {
        int s = warp + i*16;
        if (s < SEM) {
            float acc = 0.f;
            for (int o = lane; o < FEAT; o += 32) acc += s_q[o]*Wks[(size_t)s*FEAT + o];
            for (int off = 16; off; off >>= 1) acc += __shfl_xor_sync(0xffffffffu, acc, off);
            if (lane == 0) s_qsg[s] = acc * g_gatesem[b*SEM + s];
        }
    }
    __syncthreads();
    for (int i = 0; i < 19; i++) {
        int sp = warp + i*16;
        if (sp < SEMP) {
            float acc = 0.f;
            if (sp < SEM) {
                for (int s = lane; s < SEM; s += 32) acc += s_qsg[s]*W2[(size_t)sp*SEM + s];
                for (int off = 16; off; off >>= 1) acc += __shfl_xor_sync(0xffffffffu, acc, off);
            }
            if (lane == 0) g_Qcat[(size_t)idx*CAT + FEAT + sp] = (sp < SEM) ? acc : 0.f;
        }
    }
    if (warp == 0) {
        float acc = 0.f;
        for (int s = lane; s < SEM; s += 32) acc += s_qsg[s]*B2[s];
        for (int off = 16; off; off >>= 1) acc += __shfl_xor_sync(0xffffffffu, acc, off);
        if (lane == 0) g_c[idx] = acc;
    }
}

// ---------------- K6: scores = Qcat @ [BW | H]^T / TEMP ------------------------------
__global__ void k6_score(const float* __restrict__ bw, float* __restrict__ attn) {
    __shared__ __align__(16) float Qs[16][16];
    __shared__ __align__(16) float Xst[16][132];
    int b = blockIdx.y, ch = blockIdx.x;
    int n0 = ch*128;
    int nvalid = NBASE - n0; if (nvalid > 128) nvalid = 128;
    int t = threadIdx.x, lane = t & 31, warp = t >> 5;
    float acc0[4] = {0,0,0,0}, acc1[4] = {0,0,0,0};
    for (int kt = 0; kt < 51; kt++) {
        { int w = t >> 4, k = t & 15;
          Qs[w][k] = g_Qcat[(size_t)(b*NWAY + w)*CAT + kt*16 + k]; }
        #pragma unroll
        for (int i = 0; i < 2; i++) {
            int v = t + 256*i;
            int kg = v & 3, n = v >> 2;
            int kk = kt*16 + kg*4;
            float4 f = make_float4(0.f,0.f,0.f,0.f);
            if (n < nvalid) {
                if (kk < FEAT)
                    f = *reinterpret_cast<const float4*>(bw + (size_t)(b*NBASE + n0 + n)*FEAT + kk);
                else
                    f = *reinterpret_cast<const float4*>(g_H + (size_t)(b*NBASE + n0 + n)*SEMP + (kk - FEAT));
            }
            Xst[kg*4+0][n] = f.x; Xst[kg*4+1][n] = f.y; Xst[kg*4+2][n] = f.z; Xst[kg*4+3][n] = f.w;
        }
        __syncthreads();
        #pragma unroll
        for (int k = 0; k < 16; k++) {
            float q0 = Qs[warp][k];
            float q1 = Qs[warp+8][k];
            float4 x = *reinterpret_cast<const float4*>(&Xst[k][lane*4]);
            acc0[0] += q0*x.x; acc0[1] += q0*x.y; acc0[2] += q0*x.z; acc0[3] += q0*x.w;
            acc1[0] += q1*x.x; acc1[1] += q1*x.y; acc1[2] += q1*x.z; acc1[3] += q1*x.w;
        }
        __syncthreads();
    }
    float c0 = g_c[b*NWAY + warp], c1 = g_c[b*NWAY + warp + 8];
    #pragma unroll
    for (int j = 0; j < 4; j++) {
        int n = lane*4 + j;
        if (n < nvalid) {
            attn[(size_t)(b*NWAY + warp    )*NBASE + n0 + n] = (acc0[j] + c0) * INV_TEMP;
            attn[(size_t)(b*NWAY + warp + 8)*NBASE + n0 + n] = (acc1[j] + c1) * INV_TEMP;
        }
    }
}

// ---------------- K7: softmax stats --------------------------------------------------
__global__ void k7_stats(const float* __restrict__ attn) {
    __shared__ float red[256];
    int idx = blockIdx.x, t = threadIdx.x;
    const float* row = attn + (size_t)idx*NBASE;
    float m = -1e30f;
    for (int n = t; n < NBASE; n += 256) m = fmaxf(m, row[n]);
    red[t] = m; __syncthreads();
    for (int s = 128; s; s >>= 1) { if (t < s) red[t] = fmaxf(red[t], red[t+s]); __syncthreads(); }
    m = red[0]; __syncthreads();
    float z = 0.f;
    for (int n = t; n < NBASE; n += 256) z += expf(row[n] - m);
    red[t] = z; __syncthreads();
    for (int s = 128; s; s >>= 1) { if (t < s) red[t] += red[t+s]; __syncthreads(); }
    if (t == 0) { g_m[idx] = m; g_Z[idx] = red[0]; }
}

// ---------------- K8: partial attn @ base_weights ------------------------------------
__global__ void k8_part(const float* __restrict__ bw, const float* __restrict__ attn) {
    __shared__ float p[NWAY*250];
    int b = blockIdx.y, c = blockIdx.x, t = threadIdx.x;
    int n0 = c*250;
    for (int v = t; v < NWAY*250; v += 256) {
        int w = v/250, n = v%250;
        float s = attn[(size_t)(b*NWAY+w)*NBASE + n0 + n];
        p[w*250+n] = expf(s - g_m[b*NWAY+w]);
    }
    __syncthreads();
    float a0[NWAY], a1[NWAY];
    #pragma unroll
    for (int w = 0; w < NWAY; w++) { a0[w] = 0.f; a1[w] = 0.f; }
    for (int n = 0; n < 250; n++) {
        const float* r = bw + (size_t)(b*NBASE + n0 + n)*FEAT;
        float x0 = r[t], x1 = r[t+256];
        #pragma unroll
        for (int w = 0; w < NWAY; w++) {
            float pw = p[w*250+n];
            a0[w] += pw*x0; a1[w] += pw*x1;
        }
    }
    for (int w = 0; w < NWAY; w++) {
        size_t o = (size_t)((b*32 + c)*NWAY + w)*FEAT;
        g_part[o + t]       = a0[w];
        g_part[o + t + 256] = a1[w];
    }
}

// ---------------- K9: reduce partials, @Wvc, +residual -------------------------------
__global__ void k9_out(const float* __restrict__ sf, float* __restrict__ out) {
    __shared__ float s_s[FEAT];
    int idx = blockIdx.x, t = threadIdx.x;
    int b = idx >> 4, w = idx & 15;
    float acc = 0.f;
    for (int c = 0; c < 32; c++) acc += g_part[(size_t)((b*32+c)*NWAY + w)*FEAT + t];
    s_s[t] = acc / g_Z[idx];
    __syncthreads();
    float v = sf[(size_t)idx*FEAT + t];
    float a0=0.f, a1=0.f, a2=0.f, a3=0.f;
    #pragma unroll 4
    for (int d = 0; d < FEAT; d += 4) {
        a0 += s_s[d  ]*g_Wvc[(size_t)(d  )*FEAT + t];
        a1 += s_s[d+1]*g_Wvc[(size_t)(d+1)*FEAT + t];
        a2 += s_s[d+2]*g_Wvc[(size_t)(d+2)*FEAT + t];
        a3 += s_s[d+3]*g_Wvc[(size_t)(d+3)*FEAT + t];
    }
    out[(size_t)idx*FEAT + t] = v + ((a0+a1)+(a2+a3));
}

// ---------------- launch --------------------------------------------------------------
extern "C" void kernel_launch(void* const* d_in, const int* in_sizes, int n_in,
                              void* d_out, int out_size) {
    const float* sf  = (const float*)d_in[0];
    const float* bw  = (const float*)d_in[1];
    const float* ss  = (const float*)d_in[2];
    const float* bs  = (const float*)d_in[3];
    const float* w1  = (const float*)d_in[4];
    const float* b1  = (const float*)d_in[5];
    const float* w2  = (const float*)d_in[6];
    const float* b2  = (const float*)d_in[7];
    const float* vw  = (const float*)d_in[8];
    const float* vb  = (const float*)d_in[9];
    const float* swf = (const float*)d_in[10];
    const float* sb  = (const float*)d_in[11];
    const float* wq  = (const float*)d_in[12];
    const float* wk  = (const float*)d_in[13];
    const float* wv  = (const float*)d_in[14];
    const float* wqs = (const float*)d_in[15];
    const float* wks = (const float*)d_in[16];
    const float* fc  = (const float*)d_in[17];
    float* out  = (float*)d_out;
    float* attn = out + (size_t)NROW*FEAT;

    k2_pk<<<dim3(3, 500), 256>>>(bs, w1, b1);
    k1_partBW<<<dim3(16, NB), 256>>>(bw);
    k2b_partH<<<dim3(16, NB), 320>>>();
    k3_qtot<<<NROW, 512>>>(sf, ss, w1, b1, w2, b2, wq, wqs);
    k4_gates<<<NB, 512>>>(w2, b2, vw, vb, swf, sb);
    k4b_wvc<<<FEAT, 512>>>(wv, fc);
    k5_qcat<<<NROW, 512>>>(wk, wks, w2, b2);
    k6_score<<<dim3(63, NB), 256>>>(bw, attn);
    k7_stats<<<NROW, 256>>>(attn);
    k8_part<<<dim3(32, NB), 256>>>(bw, attn);
    k9_out<<<NROW, 512>>>(sf, out);
}

// round 5
// speedup vs baseline: 1.5706x; 1.4069x over previous
#include <cuda_runtime.h>
#include <cuda_bf16.h>
#include <cstdint>
#include <math.h>

#define NB 8
#define NWAY 16
#define NBASE 8000
#define FEAT 512
#define SEM 300
#define SEMP 304
#define CAT 816
#define NROW (NB*NWAY)
#define INV_TEMP 0.04419417382415922f

// ---------------- scratch ----------------
__device__ float g_H[(size_t)NB*NBASE*SEMP];
__device__ __nv_bfloat16 g_Wt[2][304*304];       // W1 transposed [n][k], hi/lo split
__device__ float g_partBW[NB*16*FEAT];
__device__ float g_partH[NB*16*SEM];
__device__ float g_gatevis[NB*FEAT];
__device__ float g_gatesem[NB*SEM];
__device__ float g_qtot[NROW*FEAT];
__device__ float g_Qcat[NROW*CAT];
__device__ float g_c[NROW];
__device__ float g_m[NROW];
__device__ float g_Z[NROW];
__device__ float g_Wvc[FEAT*FEAT];
__device__ float g_part[(size_t)NB*32*NWAY*FEAT];

// ---------------- mma helpers ----------------
__device__ __forceinline__ uint32_t smem_u32(const void* p) {
    uint32_t a;
    asm("{ .reg .u64 t; cvta.to.shared.u64 t, %1; cvt.u32.u64 %0, t; }" : "=r"(a) : "l"(p));
    return a;
}
__device__ __forceinline__ void ldsm4(uint32_t* r, uint32_t addr) {
    asm volatile("ldmatrix.sync.aligned.m8n8.x4.shared.b16 {%0,%1,%2,%3}, [%4];"
        : "=r"(r[0]), "=r"(r[1]), "=r"(r[2]), "=r"(r[3]) : "r"(addr));
}
__device__ __forceinline__ void mma_bf16(float* c, const uint32_t* a, const uint32_t* b) {
    asm volatile("mma.sync.aligned.m16n8k16.row.col.f32.bf16.bf16.f32 "
        "{%0,%1,%2,%3}, {%4,%5,%6,%7}, {%8,%9}, {%0,%1,%2,%3};"
        : "+f"(c[0]), "+f"(c[1]), "+f"(c[2]), "+f"(c[3])
        : "r"(a[0]), "r"(a[1]), "r"(a[2]), "r"(a[3]), "r"(b[0]), "r"(b[1]));
}
__device__ __forceinline__ uint32_t pack_bf2(float a, float b) {
    __nv_bfloat162 h = __floats2bfloat162_rn(a, b);
    return *reinterpret_cast<uint32_t*>(&h);
}

// ---------------- K2w: transpose + split-convert W1 to bf16 hi/lo --------------------
__global__ void k2w(const float* __restrict__ W) {
    int id = blockIdx.x*blockDim.x + threadIdx.x;
    if (id >= 304*304) return;
    int n = id / 304, k = id - n*304;
    float v = (n < SEM && k < SEM) ? W[(size_t)k*SEM + n] : 0.f;
    __nv_bfloat16 h = __float2bfloat16_rn(v);
    float lo = v - __bfloat162float(h);
    g_Wt[0][id] = h;
    g_Wt[1][id] = __float2bfloat16_rn(lo);
}

// ============ K2t: H = leaky(base_seman @ w1 + b1) via mma.sync bf16 3-term ==========
// BM=128, BN=128 (col0 in {0,128,176}; overlap recomputed; cols>=300 stored as 0),
// BK=16, 19 k-tiles, 512 threads, warp grid 4x4 (32x32 per warp), double-buffered.
#define A_STRIDE 48          // bytes per A smem row (24 bf16)
#define TILE_BYTES 6144      // 128 rows * 48B
__global__ __launch_bounds__(512) void k2t(const float* __restrict__ A,
                                           const float* __restrict__ B1v) {
    extern __shared__ __align__(16) char sm[];
    const uint32_t sb = smem_u32(sm);
    const int colTab[3] = {0, 128, 176};
    int col0 = colTab[blockIdx.x];
    int row0 = blockIdx.y * 128;
    int t = threadIdx.x, lane = t & 31, warp = t >> 5;
    int wm = warp & 3, wn = warp >> 2;

    // load-role indices
    int arow = t >> 2, akq = (t & 3) * 4;              // A: 128 rows x 16 k fp32
    int bn = t & 127, bkh = (t >> 7) & 1, bhl = t >> 8; // B: 128 n x 2 kh x hi/lo
    const float* Ap = A + (size_t)(row0 + arow) * SEM + akq;
    const __nv_bfloat16* Bp = g_Wt[bhl] + (size_t)(col0 + bn) * 304 + bkh * 8;

    float acc[2][4][4];
    #pragma unroll
    for (int i = 0; i < 2; i++)
        #pragma unroll
        for (int j = 0; j < 4; j++)
            #pragma unroll
            for (int r = 0; r < 4; r++) acc[i][j][r] = 0.f;

    // prologue: fill buffer 0 (kt=0; akq<300 always at k0=0)
    {
        float4 av = *reinterpret_cast<const float4*>(Ap);
        uint4  bv = *reinterpret_cast<const uint4*>(Bp);
        char* pa = sm + arow*A_STRIDE + akq*2;
        *reinterpret_cast<uint2*>(pa) = make_uint2(pack_bf2(av.x, av.y), pack_bf2(av.z, av.w));
        float hx = __bfloat162float(__float2bfloat16_rn(av.x));
        float hy = __bfloat162float(__float2bfloat16_rn(av.y));
        float hz = __bfloat162float(__float2bfloat16_rn(av.z));
        float hw = __bfloat162float(__float2bfloat16_rn(av.w));
        *reinterpret_cast<uint2*>(pa + TILE_BYTES) =
            make_uint2(pack_bf2(av.x-hx, av.y-hy), pack_bf2(av.z-hz, av.w-hw));
        *reinterpret_cast<uint4*>(sm + 24576 + bhl*TILE_BYTES + bn*A_STRIDE + bkh*16) = bv;
    }
    __syncthreads();

    for (int kt = 0; kt < 19; kt++) {
        int buf = kt & 1;
        float4 av2; uint4 bv2;
        if (kt < 18) {
            int k0 = (kt + 1) * 16;
            av2 = (k0 + akq < SEM) ? *reinterpret_cast<const float4*>(Ap + k0)
                                   : make_float4(0.f, 0.f, 0.f, 0.f);
            bv2 = *reinterpret_cast<const uint4*>(Bp + k0);
        }
        // ---- fragments
        uint32_t aOffH = sb + (buf*2 + 0)*TILE_BYTES;
        uint32_t aOffL = sb + (buf*2 + 1)*TILE_BYTES;
        uint32_t bOffH = sb + 24576 + (buf*2 + 0)*TILE_BYTES;
        uint32_t bOffL = sb + 24576 + (buf*2 + 1)*TILE_BYTES;
        uint32_t aF[2][2][4], bF[2][4][2];
        #pragma unroll
        for (int mt = 0; mt < 2; mt++) {
            uint32_t ra = (wm*32 + mt*16 + (lane & 15))*A_STRIDE + (lane >> 4)*16;
            ldsm4(aF[0][mt], aOffH + ra);
            ldsm4(aF[1][mt], aOffL + ra);
        }
        #pragma unroll
        for (int bt = 0; bt < 2; bt++) {
            uint32_t rb = (uint32_t)((wn*32 + bt*16 + (lane >> 4)*8 + (lane & 7))*A_STRIDE
                                     + ((lane >> 3) & 1)*16);
            uint32_t r4[4];
            ldsm4(r4, bOffH + rb);
            bF[0][2*bt][0]=r4[0]; bF[0][2*bt][1]=r4[1]; bF[0][2*bt+1][0]=r4[2]; bF[0][2*bt+1][1]=r4[3];
            ldsm4(r4, bOffL + rb);
            bF[1][2*bt][0]=r4[0]; bF[1][2*bt][1]=r4[1]; bF[1][2*bt+1][0]=r4[2]; bF[1][2*bt+1][1]=r4[3];
        }
        // ---- 3-term mma
        #pragma unroll
        for (int mt = 0; mt < 2; mt++)
            #pragma unroll
            for (int nf = 0; nf < 4; nf++) {
                mma_bf16(acc[mt][nf], aF[0][mt], bF[0][nf]);
                mma_bf16(acc[mt][nf], aF[0][mt], bF[1][nf]);
                mma_bf16(acc[mt][nf], aF[1][mt], bF[0][nf]);
            }
        __syncthreads();
        if (kt < 18) {
            int nx = buf ^ 1;
            char* pa = sm + (nx*2)*TILE_BYTES + arow*A_STRIDE + akq*2;
            *reinterpret_cast<uint2*>(pa) = make_uint2(pack_bf2(av2.x, av2.y), pack_bf2(av2.z, av2.w));
            float hx = __bfloat162float(__float2bfloat16_rn(av2.x));
            float hy = __bfloat162float(__float2bfloat16_rn(av2.y));
            float hz = __bfloat162float(__float2bfloat16_rn(av2.z));
            float hw = __bfloat162float(__float2bfloat16_rn(av2.w));
            *reinterpret_cast<uint2*>(pa + TILE_BYTES) =
                make_uint2(pack_bf2(av2.x-hx, av2.y-hy), pack_bf2(av2.z-hz, av2.w-hw));
            *reinterpret_cast<uint4*>(sm + 24576 + (nx*2 + bhl)*TILE_BYTES + bn*A_STRIDE + bkh*16) = bv2;
            __syncthreads();
        }
    }
    // ---- epilogue: bias + leaky, zero pad cols, coalesced float2 stores
    int growb = row0 + wm*32;
    int gcolb = col0 + wn*32;
    #pragma unroll
    for (int mt = 0; mt < 2; mt++)
        #pragma unroll
        for (int nf = 0; nf < 4; nf++) {
            int gr = growb + mt*16 + (lane >> 2);
            int gc = gcolb + nf*8 + (lane & 3)*2;
            float b0 = (gc     < SEM) ? B1v[gc]   : 0.f;
            float b1 = (gc + 1 < SEM) ? B1v[gc+1] : 0.f;
            float v0 = acc[mt][nf][0] + b0, v1 = acc[mt][nf][1] + b1;
            v0 = (gc     < SEM) ? ((v0 >= 0.f) ? v0 : 0.1f*v0) : 0.f;
            v1 = (gc + 1 < SEM) ? ((v1 >= 0.f) ? v1 : 0.1f*v1) : 0.f;
            *reinterpret_cast<float2*>(&g_H[(size_t)gr*SEMP + gc]) = make_float2(v0, v1);
            float v2 = acc[mt][nf][2] + b0, v3 = acc[mt][nf][3] + b1;
            v2 = (gc     < SEM) ? ((v2 >= 0.f) ? v2 : 0.1f*v2) : 0.f;
            v3 = (gc + 1 < SEM) ? ((v3 >= 0.f) ? v3 : 0.1f*v3) : 0.f;
            *reinterpret_cast<float2*>(&g_H[(size_t)(gr+8)*SEMP + gc]) = make_float2(v2, v3);
        }
}

// ---------------- K1: partial column sums of base_weights ----------------------------
__global__ void k1_partBW(const float* __restrict__ bw) {
    int b = blockIdx.y, s = blockIdx.x, t = threadIdx.x;
    int n0 = s * 500;
    const float* base = bw + ((size_t)(b*NBASE + n0))*FEAT;
    float a0 = 0.f, a1 = 0.f, a2 = 0.f, a3 = 0.f;
    #pragma unroll 2
    for (int n = 0; n < 500; n += 2) {
        const float* r0 = base + (size_t)n*FEAT;
        const float* r1 = r0 + FEAT;
        a0 += r0[t]; a1 += r0[t+256];
        a2 += r1[t]; a3 += r1[t+256];
    }
    g_partBW[(b*16+s)*FEAT + t]       = a0 + a2;
    g_partBW[(b*16+s)*FEAT + t + 256] = a1 + a3;
}

// ---------------- K2b: partial column sums of H --------------------------------------
__global__ void k2b_partH() {
    int b = blockIdx.y, s = blockIdx.x, t = threadIdx.x;
    if (t >= SEM) return;
    int n0 = s * 500;
    const float* base = g_H + ((size_t)(b*NBASE + n0))*SEMP;
    float a0 = 0.f, a1 = 0.f;
    #pragma unroll 2
    for (int n = 0; n < 500; n += 2) {
        a0 += base[(size_t)n*SEMP + t];
        a1 += base[(size_t)(n+1)*SEMP + t];
    }
    g_partH[(b*16+s)*SEM + t] = a0 + a1;
}

// ---------------- K3: support semantic calibration + q_tot ---------------------------
__global__ __launch_bounds__(512) void k3_qtot(
        const float* __restrict__ sf, const float* __restrict__ ss,
        const float* __restrict__ W1, const float* __restrict__ B1,
        const float* __restrict__ W2, const float* __restrict__ B2,
        const float* __restrict__ Wq, const float* __restrict__ Wqs) {
    __shared__ float s_ss[SEM], s_hid[SEM], s_cal[SEM], s_sf[FEAT];
    int idx = blockIdx.x, t = threadIdx.x;
    if (t < SEM) s_ss[t] = ss[(size_t)idx*SEM + t];
    s_sf[t] = sf[(size_t)idx*FEAT + t];
    __syncthreads();
    if (t < SEM) {
        float a0=0.f, a1=0.f, a2=0.f, a3=0.f;
        #pragma unroll 4
        for (int k = 0; k < SEM; k += 4) {
            a0 += s_ss[k  ]*W1[(size_t)(k  )*SEM + t];
            a1 += s_ss[k+1]*W1[(size_t)(k+1)*SEM + t];
            a2 += s_ss[k+2]*W1[(size_t)(k+2)*SEM + t];
            a3 += s_ss[k+3]*W1[(size_t)(k+3)*SEM + t];
        }
        float h = B1[t] + ((a0+a1)+(a2+a3));
        s_hid[t] = (h >= 0.f) ? h : 0.1f*h;
    }
    __syncthreads();
    if (t < SEM) {
        float a0=0.f, a1=0.f, a2=0.f, a3=0.f;
        #pragma unroll 4
        for (int k = 0; k < SEM; k += 4) {
            a0 += s_hid[k  ]*W2[(size_t)(k  )*SEM + t];
            a1 += s_hid[k+1]*W2[(size_t)(k+1)*SEM + t];
            a2 += s_hid[k+2]*W2[(size_t)(k+2)*SEM + t];
            a3 += s_hid[k+3]*W2[(size_t)(k+3)*SEM + t];
        }
        s_cal[t] = B2[t] + ((a0+a1)+(a2+a3));
    }
    __syncthreads();
    float q0=0.f, q1=0.f, q2=0.f, q3=0.f;
    #pragma unroll 4
    for (int k = 0; k < FEAT; k += 4) {
        q0 += s_sf[k  ]*Wq[(size_t)(k  )*FEAT + t];
        q1 += s_sf[k+1]*Wq[(size_t)(k+1)*FEAT + t];
        q2 += s_sf[k+2]*Wq[(size_t)(k+2)*FEAT + t];
        q3 += s_sf[k+3]*Wq[(size_t)(k+3)*FEAT + t];
    }
    #pragma unroll 4
    for (int k = 0; k < SEM; k += 4) {
        q0 += s_cal[k  ]*Wqs[(size_t)(k  )*FEAT + t];
        q1 += s_cal[k+1]*Wqs[(size_t)(k+1)*FEAT + t];
        q2 += s_cal[k+2]*Wqs[(size_t)(k+2)*FEAT + t];
        q3 += s_cal[k+3]*Wqs[(size_t)(k+3)*FEAT + t];
    }
    g_qtot[(size_t)idx*FEAT + t] = (q0+q1)+(q2+q3);
}

// ---------------- K4: means -> fusion gates ------------------------------------------
__global__ void k4_gates(const float* __restrict__ W2, const float* __restrict__ B2,
                         const float* __restrict__ Vw, const float* __restrict__ Vb,
                         const float* __restrict__ Sw, const float* __restrict__ Sb) {
    __shared__ float s_avg[FEAT + SEM];
    __shared__ float s_mh[SEM];
    int b = blockIdx.x, t = threadIdx.x;
    if (t < FEAT) {
        float a = 0.f;
        for (int s = 0; s < 16; s++) a += g_partBW[(b*16+s)*FEAT + t];
        s_avg[t] = a * (1.f/NBASE);
    }
    if (t < SEM) {
        float a = 0.f;
        for (int s = 0; s < 16; s++) a += g_partH[(b*16+s)*SEM + t];
        s_mh[t] = a * (1.f/NBASE);
    }
    __syncthreads();
    if (t < SEM) {
        float a0=0.f, a1=0.f, a2=0.f, a3=0.f;
        #pragma unroll 4
        for (int k = 0; k < SEM; k += 4) {
            a0 += s_mh[k  ]*W2[(size_t)(k  )*SEM + t];
            a1 += s_mh[k+1]*W2[(size_t)(k+1)*SEM + t];
            a2 += s_mh[k+2]*W2[(size_t)(k+2)*SEM + t];
            a3 += s_mh[k+3]*W2[(size_t)(k+3)*SEM + t];
        }
        s_avg[FEAT + t] = B2[t] + ((a0+a1)+(a2+a3));
    }
    __syncthreads();
    {
        float a0=0.f, a1=0.f, a2=0.f, a3=0.f;
        #pragma unroll 4
        for (int k = 0; k < FEAT+SEM-3; k += 4) {
            a0 += s_avg[k  ]*Vw[(size_t)(k  )*FEAT + t];
            a1 += s_avg[k+1]*Vw[(size_t)(k+1)*FEAT + t];
            a2 += s_avg[k+2]*Vw[(size_t)(k+2)*FEAT + t];
            a3 += s_avg[k+3]*Vw[(size_t)(k+3)*FEAT + t];
        }
        float g = Vb[t] + ((a0+a1)+(a2+a3));
        g_gatevis[b*FEAT + t] = 1.f + 1.f/(1.f + expf(-g));
    }
    if (t < SEM) {
        float a0=0.f, a1=0.f, a2=0.f, a3=0.f;
        #pragma unroll 4
        for (int k = 0; k < FEAT+SEM-3; k += 4) {
            a0 += s_avg[k  ]*Sw[(size_t)(k  )*SEM + t];
            a1 += s_avg[k+1]*Sw[(size_t)(k+1)*SEM + t];
            a2 += s_avg[k+2]*Sw[(size_t)(k+2)*SEM + t];
            a3 += s_avg[k+3]*Sw[(size_t)(k+3)*SEM + t];
        }
        float g = Sb[t] + ((a0+a1)+(a2+a3));
        g_gatesem[b*SEM + t] = 1.f + 1.f/(1.f + expf(-g));
    }
}

// ---------------- K4b: Wvc = w_vs @ fc_w ---------------------------------------------
__global__ void k4b_wvc(const float* __restrict__ Wv, const float* __restrict__ Fc) {
    __shared__ float s_row[FEAT];
    int r = blockIdx.x, t = threadIdx.x;
    s_row[t] = Wv[(size_t)r*FEAT + t];
    __syncthreads();
    float a0=0.f, a1=0.f, a2=0.f, a3=0.f;
    #pragma unroll 4
    for (int k = 0; k < FEAT; k += 4) {
        a0 += s_row[k  ]*Fc[(size_t)(k  )*FEAT + t];
        a1 += s_row[k+1]*Fc[(size_t)(k+1)*FEAT + t];
        a2 += s_row[k+2]*Fc[(size_t)(k+2)*FEAT + t];
        a3 += s_row[k+3]*Fc[(size_t)(k+3)*FEAT + t];
    }
    g_Wvc[(size_t)r*FEAT + t] = (a0+a1)+(a2+a3);
}

// ---------------- K5: fold W_k / gates / W2 into the query side ----------------------
__global__ void k5_qcat(const float* __restrict__ Wk, const float* __restrict__ Wks,
                        const float* __restrict__ W2, const float* __restrict__ B2) {
    __shared__ float s_q[FEAT];
    __shared__ float s_qsg[SEM];
    int idx = blockIdx.x, b = idx >> 4;
    int t = threadIdx.x, lane = t & 31, warp = t >> 5;
    s_q[t] = g_qtot[(size_t)idx*FEAT + t];
    __syncthreads();
    for (int i = 0; i < 32; i++) {
        int d = warp + i*16;
        float acc = 0.f;
        for (int o = lane; o < FEAT; o += 32) acc += s_q[o]*Wk[(size_t)d*FEAT + o];
        for (int off = 16; off; off >>= 1) acc += __shfl_xor_sync(0xffffffffu, acc, off);
        if (lane == 0) g_Qcat[(size_t)idx*CAT + d] = acc * g_gatevis[b*FEAT + d];
    }
    for (int i = 0; i < 19; i++) {
        int s = warp + i*16;
        if (s < SEM) {
            float acc = 0.f;
            for (int o = lane; o < FEAT; o += 32) acc += s_q[o]*Wks[(size_t)s*FEAT + o];
            for (int off = 16; off; off >>= 1) acc += __shfl_xor_sync(0xffffffffu, acc, off);
            if (lane == 0) s_qsg[s] = acc * g_gatesem[b*SEM + s];
        }
    }
    __syncthreads();
    for (int i = 0; i < 19; i++) {
        int sp = warp + i*16;
        if (sp < SEMP) {
            float acc = 0.f;
            if (sp < SEM) {
                for (int s = lane; s < SEM; s += 32) acc += s_qsg[s]*W2[(size_t)sp*SEM + s];
                for (int off = 16; off; off >>= 1) acc += __shfl_xor_sync(0xffffffffu, acc, off);
            }
            if (lane == 0) g_Qcat[(size_t)idx*CAT + FEAT + sp] = (sp < SEM) ? acc : 0.f;
        }
    }
    if (warp == 0) {
        float acc = 0.f;
        for (int s = lane; s < SEM; s += 32) acc += s_qsg[s]*B2[s];
        for (int off = 16; off; off >>= 1) acc += __shfl_xor_sync(0xffffffffu, acc, off);
        if (lane == 0) g_c[idx] = acc;
    }
}

// ---------------- K6: scores = Qcat @ [BW | H]^T / TEMP ------------------------------
__global__ void k6_score(const float* __restrict__ bw, float* __restrict__ attn) {
    __shared__ __align__(16) float Qs[16][16];
    __shared__ __align__(16) float Xst[16][132];
    int b = blockIdx.y, ch = blockIdx.x;
    int n0 = ch*128;
    int nvalid = NBASE - n0; if (nvalid > 128) nvalid = 128;
    int t = threadIdx.x, lane = t & 31, warp = t >> 5;
    float acc0[4] = {0,0,0,0}, acc1[4] = {0,0,0,0};
    for (int kt = 0; kt < 51; kt++) {
        { int w = t >> 4, k = t & 15;
          Qs[w][k] = g_Qcat[(size_t)(b*NWAY + w)*CAT + kt*16 + k]; }
        #pragma unroll
        for (int i = 0; i < 2; i++) {
            int v = t + 256*i;
            int kg = v & 3, n = v >> 2;
            int kk = kt*16 + kg*4;
            float4 f = make_float4(0.f,0.f,0.f,0.f);
            if (n < nvalid) {
                if (kk < FEAT)
                    f = *reinterpret_cast<const float4*>(bw + (size_t)(b*NBASE + n0 + n)*FEAT + kk);
                else
                    f = *reinterpret_cast<const float4*>(g_H + (size_t)(b*NBASE + n0 + n)*SEMP + (kk - FEAT));
            }
            Xst[kg*4+0][n] = f.x; Xst[kg*4+1][n] = f.y; Xst[kg*4+2][n] = f.z; Xst[kg*4+3][n] = f.w;
        }
        __syncthreads();
        #pragma unroll
        for (int k = 0; k < 16; k++) {
            float q0 = Qs[warp][k];
            float q1 = Qs[warp+8][k];
            float4 x = *reinterpret_cast<const float4*>(&Xst[k][lane*4]);
            acc0[0] += q0*x.x; acc0[1] += q0*x.y; acc0[2] += q0*x.z; acc0[3] += q0*x.w;
            acc1[0] += q1*x.x; acc1[1] += q1*x.y; acc1[2] += q1*x.z; acc1[3] += q1*x.w;
        }
        __syncthreads();
    }
    float c0 = g_c[b*NWAY + warp], c1 = g_c[b*NWAY + warp + 8];
    #pragma unroll
    for (int j = 0; j < 4; j++) {
        int n = lane*4 + j;
        if (n < nvalid) {
            attn[(size_t)(b*NWAY + warp    )*NBASE + n0 + n] = (acc0[j] + c0) * INV_TEMP;
            attn[(size_t)(b*NWAY + warp + 8)*NBASE + n0 + n] = (acc1[j] + c1) * INV_TEMP;
        }
    }
}

// ---------------- K7: softmax stats --------------------------------------------------
__global__ void k7_stats(const float* __restrict__ attn) {
    __shared__ float red[256];
    int idx = blockIdx.x, t = threadIdx.x;
    const float* row = attn + (size_t)idx*NBASE;
    float m = -1e30f;
    for (int n = t; n < NBASE; n += 256) m = fmaxf(m, row[n]);
    red[t] = m; __syncthreads();
    for (int s = 128; s; s >>= 1) { if (t < s) red[t] = fmaxf(red[t], red[t+s]); __syncthreads(); }
    m = red[0]; __syncthreads();
    float z = 0.f;
    for (int n = t; n < NBASE; n += 256) z += expf(row[n] - m);
    red[t] = z; __syncthreads();
    for (int s = 128; s; s >>= 1) { if (t < s) red[t] += red[t+s]; __syncthreads(); }
    if (t == 0) { g_m[idx] = m; g_Z[idx] = red[0]; }
}

// ---------------- K8: partial attn @ base_weights ------------------------------------
__global__ void k8_part(const float* __restrict__ bw, const float* __restrict__ attn) {
    __shared__ float p[NWAY*250];
    int b = blockIdx.y, c = blockIdx.x, t = threadIdx.x;
    int n0 = c*250;
    for (int v = t; v < NWAY*250; v += 256) {
        int w = v/250, n = v%250;
        float s = attn[(size_t)(b*NWAY+w)*NBASE + n0 + n];
        p[w*250+n] = expf(s - g_m[b*NWAY+w]);
    }
    __syncthreads();
    float a0[NWAY], a1[NWAY];
    #pragma unroll
    for (int w = 0; w < NWAY; w++) { a0[w] = 0.f; a1[w] = 0.f; }
    for (int n = 0; n < 250; n++) {
        const float* r = bw + (size_t)(b*NBASE + n0 + n)*FEAT;
        float x0 = r[t], x1 = r[t+256];
        #pragma unroll
        for (int w = 0; w < NWAY; w++) {
            float pw = p[w*250+n];
            a0[w] += pw*x0; a1[w] += pw*x1;
        }
    }
    for (int w = 0; w < NWAY; w++) {
        size_t o = (size_t)((b*32 + c)*NWAY + w)*FEAT;
        g_part[o + t]       = a0[w];
        g_part[o + t + 256] = a1[w];
    }
}

// ---------------- K9: reduce partials, @Wvc, +residual -------------------------------
__global__ void k9_out(const float* __restrict__ sf, float* __restrict__ out) {
    __shared__ float s_s[FEAT];
    int idx = blockIdx.x, t = threadIdx.x;
    int b = idx >> 4, w = idx & 15;
    float acc = 0.f;
    for (int c = 0; c < 32; c++) acc += g_part[(size_t)((b*32+c)*NWAY + w)*FEAT + t];
    s_s[t] = acc / g_Z[idx];
    __syncthreads();
    float v = sf[(size_t)idx*FEAT + t];
    float a0=0.f, a1=0.f, a2=0.f, a3=0.f;
    #pragma unroll 4
    for (int d = 0; d < FEAT; d += 4) {
        a0 += s_s[d  ]*g_Wvc[(size_t)(d  )*FEAT + t];
        a1 += s_s[d+1]*g_Wvc[(size_t)(d+1)*FEAT + t];
        a2 += s_s[d+2]*g_Wvc[(size_t)(d+2)*FEAT + t];
        a3 += s_s[d+3]*g_Wvc[(size_t)(d+3)*FEAT + t];
    }
    out[(size_t)idx*FEAT + t] = v + ((a0+a1)+(a2+a3));
}

// ---------------- launch --------------------------------------------------------------
extern "C" void kernel_launch(void* const* d_in, const int* in_sizes, int n_in,
                              void* d_out, int out_size) {
    const float* sf  = (const float*)d_in[0];
    const float* bw  = (const float*)d_in[1];
    const float* ss  = (const float*)d_in[2];
    const float* bs  = (const float*)d_in[3];
    const float* w1  = (const float*)d_in[4];
    const float* b1  = (const float*)d_in[5];
    const float* w2  = (const float*)d_in[6];
    const float* b2  = (const float*)d_in[7];
    const float* vw  = (const float*)d_in[8];
    const float* vb  = (const float*)d_in[9];
    const float* swf = (const float*)d_in[10];
    const float* sb  = (const float*)d_in[11];
    const float* wq  = (const float*)d_in[12];
    const float* wk  = (const float*)d_in[13];
    const float* wv  = (const float*)d_in[14];
    const float* wqs = (const float*)d_in[15];
    const float* wks = (const float*)d_in[16];
    const float* fc  = (const float*)d_in[17];
    float* out  = (float*)d_out;
    float* attn = out + (size_t)NROW*FEAT;

    cudaFuncSetAttribute(k2t, cudaFuncAttributeMaxDynamicSharedMemorySize, 49152);

    k2w<<<(304*304 + 255)/256, 256>>>(w1);
    k2t<<<dim3(3, 500), 512, 49152>>>(bs, b1);
    k1_partBW<<<dim3(16, NB), 256>>>(bw);
    k2b_partH<<<dim3(16, NB), 320>>>();
    k3_qtot<<<NROW, 512>>>(sf, ss, w1, b1, w2, b2, wq, wqs);
    k4_gates<<<NB, 512>>>(w2, b2, vw, vb, swf, sb);
    k4b_wvc<<<FEAT, 512>>>(wv, fc);
    k5_qcat<<<NROW, 512>>>(wk, wks, w2, b2);
    k6_score<<<dim3(63, NB), 256>>>(bw, attn);
    k7_stats<<<NROW, 256>>>(attn);
    k8_part<<<dim3(32, NB), 256>>>(bw, attn);
    k9_out<<<NROW, 512>>>(sf, out);
}

// round 6
// speedup vs baseline: 1.7439x; 1.1104x over previous
#include <cuda_runtime.h>
#include <cuda_bf16.h>
#include <cstdint>
#include <math.h>

#define NB 8
#define NWAY 16
#define NBASE 8000
#define FEAT 512
#define SEM 300
#define SEMP 304
#define CAT 816
#define NROW (NB*NWAY)
#define INV_TEMP 0.04419417382415922f

// ---------------- scratch ----------------
__device__ float g_H[(size_t)NB*NBASE*SEMP];
__device__ __nv_bfloat16 g_Wt[2][304*304];       // W1 transposed [n][k], hi/lo split
__device__ float g_partBW[NB*64*FEAT];
__device__ float g_partH[NB*64*SEM];
__device__ float g_gatevis[NB*FEAT];
__device__ float g_gatesem[NB*SEM];
__device__ float g_qtot[NROW*FEAT];
__device__ float g_Qcat[NROW*CAT];
__device__ float g_c[NROW];
__device__ float g_m[NROW];
__device__ float g_Z[NROW];
__device__ float g_Wvc[FEAT*FEAT];
__device__ float g_part[(size_t)NB*32*NWAY*FEAT];

// ---------------- mma helpers ----------------
__device__ __forceinline__ uint32_t smem_u32(const void* p) {
    uint32_t a;
    asm("{ .reg .u64 t; cvta.to.shared.u64 t, %1; cvt.u32.u64 %0, t; }" : "=r"(a) : "l"(p));
    return a;
}
__device__ __forceinline__ void ldsm4(uint32_t* r, uint32_t addr) {
    asm volatile("ldmatrix.sync.aligned.m8n8.x4.shared.b16 {%0,%1,%2,%3}, [%4];"
        : "=r"(r[0]), "=r"(r[1]), "=r"(r[2]), "=r"(r[3]) : "r"(addr));
}
__device__ __forceinline__ void mma_bf16(float* c, const uint32_t* a, const uint32_t* b) {
    asm volatile("mma.sync.aligned.m16n8k16.row.col.f32.bf16.bf16.f32 "
        "{%0,%1,%2,%3}, {%4,%5,%6,%7}, {%8,%9}, {%0,%1,%2,%3};"
        : "+f"(c[0]), "+f"(c[1]), "+f"(c[2]), "+f"(c[3])
        : "r"(a[0]), "r"(a[1]), "r"(a[2]), "r"(a[3]), "r"(b[0]), "r"(b[1]));
}
__device__ __forceinline__ uint32_t pack_bf2(float a, float b) {
    __nv_bfloat162 h = __floats2bfloat162_rn(a, b);
    return *reinterpret_cast<uint32_t*>(&h);
}

// ---------------- K2w: transpose + split-convert W1 to bf16 hi/lo --------------------
__global__ void k2w(const float* __restrict__ W) {
    int id = blockIdx.x*blockDim.x + threadIdx.x;
    if (id >= 304*304) return;
    int n = id / 304, k = id - n*304;
    float v = (n < SEM && k < SEM) ? W[(size_t)k*SEM + n] : 0.f;
    __nv_bfloat16 h = __float2bfloat16_rn(v);
    float lo = v - __bfloat162float(h);
    g_Wt[0][id] = h;
    g_Wt[1][id] = __float2bfloat16_rn(lo);
}

// ============ K2t: H = leaky(base_seman @ w1 + b1) via mma.sync bf16 3-term ==========
#define A_STRIDE 48
#define TILE_BYTES 6144
__global__ __launch_bounds__(512) void k2t(const float* __restrict__ A,
                                           const float* __restrict__ B1v) {
    extern __shared__ __align__(16) char sm[];
    const uint32_t sb = smem_u32(sm);
    const int colTab[3] = {0, 128, 176};
    int col0 = colTab[blockIdx.x];
    int row0 = blockIdx.y * 128;
    int t = threadIdx.x, lane = t & 31, warp = t >> 5;
    int wm = warp & 3, wn = warp >> 2;

    int arow = t >> 2, akq = (t & 3) * 4;
    int bn = t & 127, bkh = (t >> 7) & 1, bhl = t >> 8;
    const float* Ap = A + (size_t)(row0 + arow) * SEM + akq;
    const __nv_bfloat16* Bp = g_Wt[bhl] + (size_t)(col0 + bn) * 304 + bkh * 8;

    float acc[2][4][4];
    #pragma unroll
    for (int i = 0; i < 2; i++)
        #pragma unroll
        for (int j = 0; j < 4; j++)
            #pragma unroll
            for (int r = 0; r < 4; r++) acc[i][j][r] = 0.f;

    {
        float4 av = *reinterpret_cast<const float4*>(Ap);
        uint4  bv = *reinterpret_cast<const uint4*>(Bp);
        char* pa = sm + arow*A_STRIDE + akq*2;
        *reinterpret_cast<uint2*>(pa) = make_uint2(pack_bf2(av.x, av.y), pack_bf2(av.z, av.w));
        float hx = __bfloat162float(__float2bfloat16_rn(av.x));
        float hy = __bfloat162float(__float2bfloat16_rn(av.y));
        float hz = __bfloat162float(__float2bfloat16_rn(av.z));
        float hw = __bfloat162float(__float2bfloat16_rn(av.w));
        *reinterpret_cast<uint2*>(pa + TILE_BYTES) =
            make_uint2(pack_bf2(av.x-hx, av.y-hy), pack_bf2(av.z-hz, av.w-hw));
        *reinterpret_cast<uint4*>(sm + 24576 + bhl*TILE_BYTES + bn*A_STRIDE + bkh*16) = bv;
    }
    __syncthreads();

    for (int kt = 0; kt < 19; kt++) {
        int buf = kt & 1;
        float4 av2; uint4 bv2;
        if (kt < 18) {
            int k0 = (kt + 1) * 16;
            av2 = (k0 + akq < SEM) ? *reinterpret_cast<const float4*>(Ap + k0)
                                   : make_float4(0.f, 0.f, 0.f, 0.f);
            bv2 = *reinterpret_cast<const uint4*>(Bp + k0);
        }
        uint32_t aOffH = sb + (buf*2 + 0)*TILE_BYTES;
        uint32_t aOffL = sb + (buf*2 + 1)*TILE_BYTES;
        uint32_t bOffH = sb + 24576 + (buf*2 + 0)*TILE_BYTES;
        uint32_t bOffL = sb + 24576 + (buf*2 + 1)*TILE_BYTES;
        uint32_t aF[2][2][4], bF[2][4][2];
        #pragma unroll
        for (int mt = 0; mt < 2; mt++) {
            uint32_t ra = (wm*32 + mt*16 + (lane & 15))*A_STRIDE + (lane >> 4)*16;
            ldsm4(aF[0][mt], aOffH + ra);
            ldsm4(aF[1][mt], aOffL + ra);
        }
        #pragma unroll
        for (int bt = 0; bt < 2; bt++) {
            uint32_t rb = (uint32_t)((wn*32 + bt*16 + (lane >> 4)*8 + (lane & 7))*A_STRIDE
                                     + ((lane >> 3) & 1)*16);
            uint32_t r4[4];
            ldsm4(r4, bOffH + rb);
            bF[0][2*bt][0]=r4[0]; bF[0][2*bt][1]=r4[1]; bF[0][2*bt+1][0]=r4[2]; bF[0][2*bt+1][1]=r4[3];
            ldsm4(r4, bOffL + rb);
            bF[1][2*bt][0]=r4[0]; bF[1][2*bt][1]=r4[1]; bF[1][2*bt+1][0]=r4[2]; bF[1][2*bt+1][1]=r4[3];
        }
        #pragma unroll
        for (int mt = 0; mt < 2; mt++)
            #pragma unroll
            for (int nf = 0; nf < 4; nf++) {
                mma_bf16(acc[mt][nf], aF[0][mt], bF[0][nf]);
                mma_bf16(acc[mt][nf], aF[0][mt], bF[1][nf]);
                mma_bf16(acc[mt][nf], aF[1][mt], bF[0][nf]);
            }
        __syncthreads();
        if (kt < 18) {
            int nx = buf ^ 1;
            char* pa = sm + (nx*2)*TILE_BYTES + arow*A_STRIDE + akq*2;
            *reinterpret_cast<uint2*>(pa) = make_uint2(pack_bf2(av2.x, av2.y), pack_bf2(av2.z, av2.w));
            float hx = __bfloat162float(__float2bfloat16_rn(av2.x));
            float hy = __bfloat162float(__float2bfloat16_rn(av2.y));
            float hz = __bfloat162float(__float2bfloat16_rn(av2.z));
            float hw = __bfloat162float(__float2bfloat16_rn(av2.w));
            *reinterpret_cast<uint2*>(pa + TILE_BYTES) =
                make_uint2(pack_bf2(av2.x-hx, av2.y-hy), pack_bf2(av2.z-hz, av2.w-hw));
            *reinterpret_cast<uint4*>(sm + 24576 + (nx*2 + bhl)*TILE_BYTES + bn*A_STRIDE + bkh*16) = bv2;
            __syncthreads();
        }
    }
    int growb = row0 + wm*32;
    int gcolb = col0 + wn*32;
    #pragma unroll
    for (int mt = 0; mt < 2; mt++)
        #pragma unroll
        for (int nf = 0; nf < 4; nf++) {
            int gr = growb + mt*16 + (lane >> 2);
            int gc = gcolb + nf*8 + (lane & 3)*2;
            float b0 = (gc     < SEM) ? B1v[gc]   : 0.f;
            float b1 = (gc + 1 < SEM) ? B1v[gc+1] : 0.f;
            float v0 = acc[mt][nf][0] + b0, v1 = acc[mt][nf][1] + b1;
            v0 = (gc     < SEM) ? ((v0 >= 0.f) ? v0 : 0.1f*v0) : 0.f;
            v1 = (gc + 1 < SEM) ? ((v1 >= 0.f) ? v1 : 0.1f*v1) : 0.f;
            *reinterpret_cast<float2*>(&g_H[(size_t)gr*SEMP + gc]) = make_float2(v0, v1);
            float v2 = acc[mt][nf][2] + b0, v3 = acc[mt][nf][3] + b1;
            v2 = (gc     < SEM) ? ((v2 >= 0.f) ? v2 : 0.1f*v2) : 0.f;
            v3 = (gc + 1 < SEM) ? ((v3 >= 0.f) ? v3 : 0.1f*v3) : 0.f;
            *reinterpret_cast<float2*>(&g_H[(size_t)(gr+8)*SEMP + gc]) = make_float2(v2, v3);
        }
}

// ---------------- K1: partial column sums of base_weights (64 chunks of 125) ---------
__global__ void k1_partBW(const float* __restrict__ bw) {
    int b = blockIdx.y, s = blockIdx.x, t = threadIdx.x;
    int n0 = s * 125;
    const float* base = bw + ((size_t)(b*NBASE + n0))*FEAT;
    float a0 = 0.f, a1 = 0.f;
    #pragma unroll 4
    for (int n = 0; n < 125; n++) {
        const float* r = base + (size_t)n*FEAT;
        a0 += r[t]; a1 += r[t+256];
    }
    g_partBW[(b*64+s)*FEAT + t]       = a0;
    g_partBW[(b*64+s)*FEAT + t + 256] = a1;
}

// ---------------- K2b: partial column sums of H (64 chunks of 125) -------------------
__global__ void k2b_partH() {
    int b = blockIdx.y, s = blockIdx.x, t = threadIdx.x;
    if (t >= SEM) return;
    int n0 = s * 125;
    const float* base = g_H + ((size_t)(b*NBASE + n0))*SEMP;
    float a0 = 0.f;
    #pragma unroll 8
    for (int n = 0; n < 125; n++) a0 += base[(size_t)n*SEMP + t];
    g_partH[(b*64+s)*SEM + t] = a0;
}

// ---------------- K3: support semantic calibration + q_tot ---------------------------
__global__ __launch_bounds__(512) void k3_qtot(
        const float* __restrict__ sf, const float* __restrict__ ss,
        const float* __restrict__ W1, const float* __restrict__ B1,
        const float* __restrict__ W2, const float* __restrict__ B2,
        const float* __restrict__ Wq, const float* __restrict__ Wqs) {
    __shared__ float s_ss[SEM], s_hid[SEM], s_cal[SEM], s_sf[FEAT];
    int idx = blockIdx.x, t = threadIdx.x;
    if (t < SEM) s_ss[t] = ss[(size_t)idx*SEM + t];
    s_sf[t] = sf[(size_t)idx*FEAT + t];
    __syncthreads();
    if (t < SEM) {
        float a0=0.f, a1=0.f, a2=0.f, a3=0.f;
        #pragma unroll 8
        for (int k = 0; k < SEM; k += 4) {
            a0 += s_ss[k  ]*W1[(size_t)(k  )*SEM + t];
            a1 += s_ss[k+1]*W1[(size_t)(k+1)*SEM + t];
            a2 += s_ss[k+2]*W1[(size_t)(k+2)*SEM + t];
            a3 += s_ss[k+3]*W1[(size_t)(k+3)*SEM + t];
        }
        float h = B1[t] + ((a0+a1)+(a2+a3));
        s_hid[t] = (h >= 0.f) ? h : 0.1f*h;
    }
    __syncthreads();
    if (t < SEM) {
        float a0=0.f, a1=0.f, a2=0.f, a3=0.f;
        #pragma unroll 8
        for (int k = 0; k < SEM; k += 4) {
            a0 += s_hid[k  ]*W2[(size_t)(k  )*SEM + t];
            a1 += s_hid[k+1]*W2[(size_t)(k+1)*SEM + t];
            a2 += s_hid[k+2]*W2[(size_t)(k+2)*SEM + t];
            a3 += s_hid[k+3]*W2[(size_t)(k+3)*SEM + t];
        }
        s_cal[t] = B2[t] + ((a0+a1)+(a2+a3));
    }
    __syncthreads();
    float q0=0.f, q1=0.f, q2=0.f, q3=0.f;
    #pragma unroll 8
    for (int k = 0; k < FEAT; k += 4) {
        q0 += s_sf[k  ]*Wq[(size_t)(k  )*FEAT + t];
        q1 += s_sf[k+1]*Wq[(size_t)(k+1)*FEAT + t];
        q2 += s_sf[k+2]*Wq[(size_t)(k+2)*FEAT + t];
        q3 += s_sf[k+3]*Wq[(size_t)(k+3)*FEAT + t];
    }
    #pragma unroll 8
    for (int k = 0; k < SEM; k += 4) {
        q0 += s_cal[k  ]*Wqs[(size_t)(k  )*FEAT + t];
        q1 += s_cal[k+1]*Wqs[(size_t)(k+1)*FEAT + t];
        q2 += s_cal[k+2]*Wqs[(size_t)(k+2)*FEAT + t];
        q3 += s_cal[k+3]*Wqs[(size_t)(k+3)*FEAT + t];
    }
    g_qtot[(size_t)idx*FEAT + t] = (q0+q1)+(q2+q3);
}

// ---------------- K4: means -> fusion gates (64 partials) ----------------------------
__global__ void k4_gates(const float* __restrict__ W2, const float* __restrict__ B2,
                         const float* __restrict__ Vw, const float* __restrict__ Vb,
                         const float* __restrict__ Sw, const float* __restrict__ Sb) {
    __shared__ float s_avg[FEAT + SEM];
    __shared__ float s_mh[SEM];
    int b = blockIdx.x, t = threadIdx.x;
    if (t < FEAT) {
        float a = 0.f;
        #pragma unroll 4
        for (int s = 0; s < 64; s++) a += g_partBW[(b*64+s)*FEAT + t];
        s_avg[t] = a * (1.f/NBASE);
    }
    if (t < SEM) {
        float a = 0.f;
        #pragma unroll 4
        for (int s = 0; s < 64; s++) a += g_partH[(b*64+s)*SEM + t];
        s_mh[t] = a * (1.f/NBASE);
    }
    __syncthreads();
    if (t < SEM) {
        float a0=0.f, a1=0.f, a2=0.f, a3=0.f;
        #pragma unroll 8
        for (int k = 0; k < SEM; k += 4) {
            a0 += s_mh[k  ]*W2[(size_t)(k  )*SEM + t];
            a1 += s_mh[k+1]*W2[(size_t)(k+1)*SEM + t];
            a2 += s_mh[k+2]*W2[(size_t)(k+2)*SEM + t];
            a3 += s_mh[k+3]*W2[(size_t)(k+3)*SEM + t];
        }
        s_avg[FEAT + t] = B2[t] + ((a0+a1)+(a2+a3));
    }
    __syncthreads();
    {
        float a0=0.f, a1=0.f, a2=0.f, a3=0.f;
        #pragma unroll 8
        for (int k = 0; k < FEAT+SEM-3; k += 4) {
            a0 += s_avg[k  ]*Vw[(size_t)(k  )*FEAT + t];
            a1 += s_avg[k+1]*Vw[(size_t)(k+1)*FEAT + t];
            a2 += s_avg[k+2]*Vw[(size_t)(k+2)*FEAT + t];
            a3 += s_avg[k+3]*Vw[(size_t)(k+3)*FEAT + t];
        }
        float g = Vb[t] + ((a0+a1)+(a2+a3));
        g_gatevis[b*FEAT + t] = 1.f + 1.f/(1.f + expf(-g));
    }
    if (t < SEM) {
        float a0=0.f, a1=0.f, a2=0.f, a3=0.f;
        #pragma unroll 8
        for (int k = 0; k < FEAT+SEM-3; k += 4) {
            a0 += s_avg[k  ]*Sw[(size_t)(k  )*SEM + t];
            a1 += s_avg[k+1]*Sw[(size_t)(k+1)*SEM + t];
            a2 += s_avg[k+2]*Sw[(size_t)(k+2)*SEM + t];
            a3 += s_avg[k+3]*Sw[(size_t)(k+3)*SEM + t];
        }
        float g = Sb[t] + ((a0+a1)+(a2+a3));
        g_gatesem[b*SEM + t] = 1.f + 1.f/(1.f + expf(-g));
    }
}

// ---------------- K4b: Wvc = w_vs @ fc_w (4 rows/block, grid 128) --------------------
__global__ __launch_bounds__(512) void k4b_wvc(const float* __restrict__ Wv,
                                               const float* __restrict__ Fc) {
    __shared__ float s_row[4][FEAT];
    int r0 = blockIdx.x*4, t = threadIdx.x;
    #pragma unroll
    for (int r = 0; r < 4; r++) s_row[r][t] = Wv[(size_t)(r0+r)*FEAT + t];
    __syncthreads();
    float a0=0.f, a1=0.f, a2=0.f, a3=0.f;
    #pragma unroll 4
    for (int k = 0; k < FEAT; k++) {
        float f = Fc[(size_t)k*FEAT + t];
        a0 += s_row[0][k]*f; a1 += s_row[1][k]*f;
        a2 += s_row[2][k]*f; a3 += s_row[3][k]*f;
    }
    g_Wvc[(size_t)(r0+0)*FEAT + t] = a0;
    g_Wvc[(size_t)(r0+1)*FEAT + t] = a1;
    g_Wvc[(size_t)(r0+2)*FEAT + t] = a2;
    g_Wvc[(size_t)(r0+3)*FEAT + t] = a3;
}

// ---------------- K5: fold W_k / gates / W2 into the query side ----------------------
__global__ void k5_qcat(const float* __restrict__ Wk, const float* __restrict__ Wks,
                        const float* __restrict__ W2, const float* __restrict__ B2) {
    __shared__ float s_q[FEAT];
    __shared__ float s_qsg[SEM];
    int idx = blockIdx.x, b = idx >> 4;
    int t = threadIdx.x, lane = t & 31, warp = t >> 5;
    s_q[t] = g_qtot[(size_t)idx*FEAT + t];
    __syncthreads();
    for (int i = 0; i < 32; i++) {
        int d = warp + i*16;
        float acc = 0.f;
        #pragma unroll
        for (int o = lane; o < FEAT; o += 32) acc += s_q[o]*Wk[(size_t)d*FEAT + o];
        for (int off = 16; off; off >>= 1) acc += __shfl_xor_sync(0xffffffffu, acc, off);
        if (lane == 0) g_Qcat[(size_t)idx*CAT + d] = acc * g_gatevis[b*FEAT + d];
    }
    for (int i = 0; i < 19; i++) {
        int s = warp + i*16;
        if (s < SEM) {
            float acc = 0.f;
            #pragma unroll
            for (int o = lane; o < FEAT; o += 32) acc += s_q[o]*Wks[(size_t)s*FEAT + o];
            for (int off = 16; off; off >>= 1) acc += __shfl_xor_sync(0xffffffffu, acc, off);
            if (lane == 0) s_qsg[s] = acc * g_gatesem[b*SEM + s];
        }
    }
    __syncthreads();
    for (int i = 0; i < 19; i++) {
        int sp = warp + i*16;
        if (sp < SEMP) {
            float acc = 0.f;
            if (sp < SEM) {
                for (int s = lane; s < SEM; s += 32) acc += s_qsg[s]*W2[(size_t)sp*SEM + s];
                for (int off = 16; off; off >>= 1) acc += __shfl_xor_sync(0xffffffffu, acc, off);
            }
            if (lane == 0) g_Qcat[(size_t)idx*CAT + FEAT + sp] = (sp < SEM) ? acc : 0.f;
        }
    }
    if (warp == 0) {
        float acc = 0.f;
        for (int s = lane; s < SEM; s += 32) acc += s_qsg[s]*B2[s];
        for (int off = 16; off; off >>= 1) acc += __shfl_xor_sync(0xffffffffu, acc, off);
        if (lane == 0) g_c[idx] = acc;
    }
}

// ---------------- K6: scores = Qcat @ [BW | H]^T / TEMP ------------------------------
__global__ void k6_score(const float* __restrict__ bw, float* __restrict__ attn) {
    __shared__ __align__(16) float Qs[16][16];
    __shared__ __align__(16) float Xst[16][132];
    int b = blockIdx.y, ch = blockIdx.x;
    int n0 = ch*128;
    int nvalid = NBASE - n0; if (nvalid > 128) nvalid = 128;
    int t = threadIdx.x, lane = t & 31, warp = t >> 5;
    float acc0[4] = {0,0,0,0}, acc1[4] = {0,0,0,0};
    for (int kt = 0; kt < 51; kt++) {
        { int w = t >> 4, k = t & 15;
          Qs[w][k] = g_Qcat[(size_t)(b*NWAY + w)*CAT + kt*16 + k]; }
        #pragma unroll
        for (int i = 0; i < 2; i++) {
            int v = t + 256*i;
            int kg = v & 3, n = v >> 2;
            int kk = kt*16 + kg*4;
            float4 f = make_float4(0.f,0.f,0.f,0.f);
            if (n < nvalid) {
                if (kk < FEAT)
                    f = *reinterpret_cast<const float4*>(bw + (size_t)(b*NBASE + n0 + n)*FEAT + kk);
                else
                    f = *reinterpret_cast<const float4*>(g_H + (size_t)(b*NBASE + n0 + n)*SEMP + (kk - FEAT));
            }
            Xst[kg*4+0][n] = f.x; Xst[kg*4+1][n] = f.y; Xst[kg*4+2][n] = f.z; Xst[kg*4+3][n] = f.w;
        }
        __syncthreads();
        #pragma unroll
        for (int k = 0; k < 16; k++) {
            float q0 = Qs[warp][k];
            float q1 = Qs[warp+8][k];
            float4 x = *reinterpret_cast<const float4*>(&Xst[k][lane*4]);
            acc0[0] += q0*x.x; acc0[1] += q0*x.y; acc0[2] += q0*x.z; acc0[3] += q0*x.w;
            acc1[0] += q1*x.x; acc1[1] += q1*x.y; acc1[2] += q1*x.z; acc1[3] += q1*x.w;
        }
        __syncthreads();
    }
    float c0 = g_c[b*NWAY + warp], c1 = g_c[b*NWAY + warp + 8];
    #pragma unroll
    for (int j = 0; j < 4; j++) {
        int n = lane*4 + j;
        if (n < nvalid) {
            attn[(size_t)(b*NWAY + warp    )*NBASE + n0 + n] = (acc0[j] + c0) * INV_TEMP;
            attn[(size_t)(b*NWAY + warp + 8)*NBASE + n0 + n] = (acc1[j] + c1) * INV_TEMP;
        }
    }
}

// ---------------- K7: softmax stats --------------------------------------------------
__global__ void k7_stats(const float* __restrict__ attn) {
    __shared__ float red[256];
    int idx = blockIdx.x, t = threadIdx.x;
    const float* row = attn + (size_t)idx*NBASE;
    float m = -1e30f;
    for (int n = t; n < NBASE; n += 256) m = fmaxf(m, row[n]);
    red[t] = m; __syncthreads();
    for (int s = 128; s; s >>= 1) { if (t < s) red[t] = fmaxf(red[t], red[t+s]); __syncthreads(); }
    m = red[0]; __syncthreads();
    float z = 0.f;
    for (int n = t; n < NBASE; n += 256) z += expf(row[n] - m);
    red[t] = z; __syncthreads();
    for (int s = 128; s; s >>= 1) { if (t < s) red[t] += red[t+s]; __syncthreads(); }
    if (t == 0) { g_m[idx] = m; g_Z[idx] = red[0]; }
}

// ---------------- K8: partial attn @ base_weights ------------------------------------
__global__ void k8_part(const float* __restrict__ bw, const float* __restrict__ attn) {
    __shared__ float p[NWAY*250];
    int b = blockIdx.y, c = blockIdx.x, t = threadIdx.x;
    int n0 = c*250;
    for (int v = t; v < NWAY*250; v += 256) {
        int w = v/250, n = v%250;
        float s = attn[(size_t)(b*NWAY+w)*NBASE + n0 + n];
        p[w*250+n] = expf(s - g_m[b*NWAY+w]);
    }
    __syncthreads();
    float a0[NWAY], a1[NWAY];
    #pragma unroll
    for (int w = 0; w < NWAY; w++) { a0[w] = 0.f; a1[w] = 0.f; }
    for (int n = 0; n < 250; n++) {
        const float* r = bw + (size_t)(b*NBASE + n0 + n)*FEAT;
        float x0 = r[t], x1 = r[t+256];
        #pragma unroll
        for (int w = 0; w < NWAY; w++) {
            float pw = p[w*250+n];
            a0[w] += pw*x0; a1[w] += pw*x1;
        }
    }
    for (int w = 0; w < NWAY; w++) {
        size_t o = (size_t)((b*32 + c)*NWAY + w)*FEAT;
        g_part[o + t]       = a0[w];
        g_part[o + t + 256] = a1[w];
    }
}

// ---------------- K9: reduce partials, @Wvc, +residual -------------------------------
__global__ void k9_out(const float* __restrict__ sf, float* __restrict__ out) {
    __shared__ float s_s[FEAT];
    int idx = blockIdx.x, t = threadIdx.x;
    int b = idx >> 4, w = idx & 15;
    float acc = 0.f;
    #pragma unroll 4
    for (int c = 0; c < 32; c++) acc += g_part[(size_t)((b*32+c)*NWAY + w)*FEAT + t];
    s_s[t] = acc / g_Z[idx];
    __syncthreads();
    float v = sf[(size_t)idx*FEAT + t];
    float a0=0.f, a1=0.f, a2=0.f, a3=0.f;
    #pragma unroll 8
    for (int d = 0; d < FEAT; d += 4) {
        a0 += s_s[d  ]*g_Wvc[(size_t)(d  )*FEAT + t];
        a1 += s_s[d+1]*g_Wvc[(size_t)(d+1)*FEAT + t];
        a2 += s_s[d+2]*g_Wvc[(size_t)(d+2)*FEAT + t];
        a3 += s_s[d+3]*g_Wvc[(size_t)(d+3)*FEAT + t];
    }
    out[(size_t)idx*FEAT + t] = v + ((a0+a1)+(a2+a3));
}

// ---------------- launch --------------------------------------------------------------
extern "C" void kernel_launch(void* const* d_in, const int* in_sizes, int n_in,
                              void* d_out, int out_size) {
    const float* sf  = (const float*)d_in[0];
    const float* bw  = (const float*)d_in[1];
    const float* ss  = (const float*)d_in[2];
    const float* bs  = (const float*)d_in[3];
    const float* w1  = (const float*)d_in[4];
    const float* b1  = (const float*)d_in[5];
    const float* w2  = (const float*)d_in[6];
    const float* b2  = (const float*)d_in[7];
    const float* vw  = (const float*)d_in[8];
    const float* vb  = (const float*)d_in[9];
    const float* swf = (const float*)d_in[10];
    const float* sb  = (const float*)d_in[11];
    const float* wq  = (const float*)d_in[12];
    const float* wk  = (const float*)d_in[13];
    const float* wv  = (const float*)d_in[14];
    const float* wqs = (const float*)d_in[15];
    const float* wks = (const float*)d_in[16];
    const float* fc  = (const float*)d_in[17];
    float* out  = (float*)d_out;
    float* attn = out + (size_t)NROW*FEAT;

    cudaFuncSetAttribute(k2t, cudaFuncAttributeMaxDynamicSharedMemorySize, 49152);

    k2w<<<(304*304 + 255)/256, 256>>>(w1);
    k2t<<<dim3(3, 500), 512, 49152>>>(bs, b1);
    k1_partBW<<<dim3(64, NB), 256>>>(bw);
    k2b_partH<<<dim3(64, NB), 320>>>();
    k3_qtot<<<NROW, 512>>>(sf, ss, w1, b1, w2, b2, wq, wqs);
    k4_gates<<<NB, 512>>>(w2, b2, vw, vb, swf, sb);
    k4b_wvc<<<128, 512>>>(wv, fc);
    k5_qcat<<<NROW, 512>>>(wk, wks, w2, b2);
    k6_score<<<dim3(63, NB), 256>>>(bw, attn);
    k7_stats<<<NROW, 256>>>(attn);
    k8_part<<<dim3(32, NB), 256>>>(bw, attn);
    k9_out<<<NROW, 512>>>(sf, out);
}

// round 7
// speedup vs baseline: 1.8387x; 1.0544x over previous
#include <cuda_runtime.h>
#include <cuda_bf16.h>
#include <cstdint>
#include <math.h>

#define NB 8
#define NWAY 16
#define NBASE 8000
#define FEAT 512
#define SEM 300
#define SEMP 304
#define CAT 816
#define NROW (NB*NWAY)
#define NCHUNK 63
#define INV_TEMP 0.04419417382415922f

// ---------------- scratch ----------------
__device__ float g_H[(size_t)NB*NBASE*SEMP];
__device__ __nv_bfloat16 g_Wt[2][304*304];
__device__ float g_partBW[NB*64*FEAT];
__device__ float g_partH[NB*64*SEM];
__device__ float g_gatevis[NB*FEAT];
__device__ float g_gatesem[NB*SEM];
__device__ float g_qtot[NROW*FEAT];
__device__ float g_Qcat[NROW*CAT];
__device__ float g_c[NROW];
__device__ float g_m[NROW];
__device__ float g_Z[NROW];
__device__ float g_pm[NROW*NCHUNK];
__device__ float g_pz[NROW*NCHUNK];
__device__ float g_Wvc[FEAT*FEAT];
__device__ float g_part[(size_t)NB*32*NWAY*FEAT];

// ---------------- helpers ----------------
__device__ __forceinline__ uint32_t smem_u32(const void* p) {
    uint32_t a;
    asm("{ .reg .u64 t; cvta.to.shared.u64 t, %1; cvt.u32.u64 %0, t; }" : "=r"(a) : "l"(p));
    return a;
}
__device__ __forceinline__ void ldsm4(uint32_t* r, uint32_t addr) {
    asm volatile("ldmatrix.sync.aligned.m8n8.x4.shared.b16 {%0,%1,%2,%3}, [%4];"
        : "=r"(r[0]), "=r"(r[1]), "=r"(r[2]), "=r"(r[3]) : "r"(addr));
}
__device__ __forceinline__ void mma_bf16(float* c, const uint32_t* a, const uint32_t* b) {
    asm volatile("mma.sync.aligned.m16n8k16.row.col.f32.bf16.bf16.f32 "
        "{%0,%1,%2,%3}, {%4,%5,%6,%7}, {%8,%9}, {%0,%1,%2,%3};"
        : "+f"(c[0]), "+f"(c[1]), "+f"(c[2]), "+f"(c[3])
        : "r"(a[0]), "r"(a[1]), "r"(a[2]), "r"(a[3]), "r"(b[0]), "r"(b[1]));
}
__device__ __forceinline__ uint32_t pack_bf2(float a, float b) {
    __nv_bfloat162 h = __floats2bfloat162_rn(a, b);
    return *reinterpret_cast<uint32_t*>(&h);
}
__device__ __forceinline__ unsigned long long f2fma(unsigned long long a, unsigned long long b, unsigned long long c) {
    unsigned long long d;
    asm("fma.rn.f32x2 %0, %1, %2, %3;" : "=l"(d) : "l"(a), "l"(b), "l"(c));
    return d;
}
__device__ __forceinline__ unsigned long long f2pk(float x, float y) {
    unsigned long long r;
    asm("mov.b64 %0, {%1, %2};" : "=l"(r) : "f"(x), "f"(y));
    return r;
}
__device__ __forceinline__ void f2up(unsigned long long v, float& x, float& y) {
    asm("mov.b64 {%0, %1}, %2;" : "=f"(x), "=f"(y) : "l"(v));
}

// ---------------- K2w: transpose + split-convert W1 to bf16 hi/lo --------------------
__global__ void k2w(const float* __restrict__ W) {
    int id = blockIdx.x*blockDim.x + threadIdx.x;
    if (id >= 304*304) return;
    int n = id / 304, k = id - n*304;
    float v = (n < SEM && k < SEM) ? W[(size_t)k*SEM + n] : 0.f;
    __nv_bfloat16 h = __float2bfloat16_rn(v);
    float lo = v - __bfloat162float(h);
    g_Wt[0][id] = h;
    g_Wt[1][id] = __float2bfloat16_rn(lo);
}

// ============ K2t: H = leaky(base_seman @ w1 + b1) via mma.sync bf16 3-term ==========
#define A_STRIDE 48
#define TILE_BYTES 6144
__global__ __launch_bounds__(512) void k2t(const float* __restrict__ A,
                                           const float* __restrict__ B1v) {
    extern __shared__ __align__(16) char sm[];
    const uint32_t sb = smem_u32(sm);
    const int colTab[3] = {0, 128, 176};
    int col0 = colTab[blockIdx.x];
    int row0 = blockIdx.y * 128;
    int t = threadIdx.x, lane = t & 31, warp = t >> 5;
    int wm = warp & 3, wn = warp >> 2;

    int arow = t >> 2, akq = (t & 3) * 4;
    int bn = t & 127, bkh = (t >> 7) & 1, bhl = t >> 8;
    const float* Ap = A + (size_t)(row0 + arow) * SEM + akq;
    const __nv_bfloat16* Bp = g_Wt[bhl] + (size_t)(col0 + bn) * 304 + bkh * 8;

    float acc[2][4][4];
    #pragma unroll
    for (int i = 0; i < 2; i++)
        #pragma unroll
        for (int j = 0; j < 4; j++)
            #pragma unroll
            for (int r = 0; r < 4; r++) acc[i][j][r] = 0.f;

    {
        float4 av = *reinterpret_cast<const float4*>(Ap);
        uint4  bv = *reinterpret_cast<const uint4*>(Bp);
        char* pa = sm + arow*A_STRIDE + akq*2;
        *reinterpret_cast<uint2*>(pa) = make_uint2(pack_bf2(av.x, av.y), pack_bf2(av.z, av.w));
        float hx = __bfloat162float(__float2bfloat16_rn(av.x));
        float hy = __bfloat162float(__float2bfloat16_rn(av.y));
        float hz = __bfloat162float(__float2bfloat16_rn(av.z));
        float hw = __bfloat162float(__float2bfloat16_rn(av.w));
        *reinterpret_cast<uint2*>(pa + TILE_BYTES) =
            make_uint2(pack_bf2(av.x-hx, av.y-hy), pack_bf2(av.z-hz, av.w-hw));
        *reinterpret_cast<uint4*>(sm + 24576 + bhl*TILE_BYTES + bn*A_STRIDE + bkh*16) = bv;
    }
    __syncthreads();

    for (int kt = 0; kt < 19; kt++) {
        int buf = kt & 1;
        float4 av2; uint4 bv2;
        if (kt < 18) {
            int k0 = (kt + 1) * 16;
            av2 = (k0 + akq < SEM) ? *reinterpret_cast<const float4*>(Ap + k0)
                                   : make_float4(0.f, 0.f, 0.f, 0.f);
            bv2 = *reinterpret_cast<const uint4*>(Bp + k0);
        }
        uint32_t aOffH = sb + (buf*2 + 0)*TILE_BYTES;
        uint32_t aOffL = sb + (buf*2 + 1)*TILE_BYTES;
        uint32_t bOffH = sb + 24576 + (buf*2 + 0)*TILE_BYTES;
        uint32_t bOffL = sb + 24576 + (buf*2 + 1)*TILE_BYTES;
        uint32_t aF[2][2][4], bF[2][4][2];
        #pragma unroll
        for (int mt = 0; mt < 2; mt++) {
            uint32_t ra = (wm*32 + mt*16 + (lane & 15))*A_STRIDE + (lane >> 4)*16;
            ldsm4(aF[0][mt], aOffH + ra);
            ldsm4(aF[1][mt], aOffL + ra);
        }
        #pragma unroll
        for (int bt = 0; bt < 2; bt++) {
            uint32_t rb = (uint32_t)((wn*32 + bt*16 + (lane >> 4)*8 + (lane & 7))*A_STRIDE
                                     + ((lane >> 3) & 1)*16);
            uint32_t r4[4];
            ldsm4(r4, bOffH + rb);
            bF[0][2*bt][0]=r4[0]; bF[0][2*bt][1]=r4[1]; bF[0][2*bt+1][0]=r4[2]; bF[0][2*bt+1][1]=r4[3];
            ldsm4(r4, bOffL + rb);
            bF[1][2*bt][0]=r4[0]; bF[1][2*bt][1]=r4[1]; bF[1][2*bt+1][0]=r4[2]; bF[1][2*bt+1][1]=r4[3];
        }
        #pragma unroll
        for (int mt = 0; mt < 2; mt++)
            #pragma unroll
            for (int nf = 0; nf < 4; nf++) {
                mma_bf16(acc[mt][nf], aF[0][mt], bF[0][nf]);
                mma_bf16(acc[mt][nf], aF[0][mt], bF[1][nf]);
                mma_bf16(acc[mt][nf], aF[1][mt], bF[0][nf]);
            }
        __syncthreads();
        if (kt < 18) {
            int nx = buf ^ 1;
            char* pa = sm + (nx*2)*TILE_BYTES + arow*A_STRIDE + akq*2;
            *reinterpret_cast<uint2*>(pa) = make_uint2(pack_bf2(av2.x, av2.y), pack_bf2(av2.z, av2.w));
            float hx = __bfloat162float(__float2bfloat16_rn(av2.x));
            float hy = __bfloat162float(__float2bfloat16_rn(av2.y));
            float hz = __bfloat162float(__float2bfloat16_rn(av2.z));
            float hw = __bfloat162float(__float2bfloat16_rn(av2.w));
            *reinterpret_cast<uint2*>(pa + TILE_BYTES) =
                make_uint2(pack_bf2(av2.x-hx, av2.y-hy), pack_bf2(av2.z-hz, av2.w-hw));
            *reinterpret_cast<uint4*>(sm + 24576 + (nx*2 + bhl)*TILE_BYTES + bn*A_STRIDE + bkh*16) = bv2;
            __syncthreads();
        }
    }
    int growb = row0 + wm*32;
    int gcolb = col0 + wn*32;
    #pragma unroll
    for (int mt = 0; mt < 2; mt++)
        #pragma unroll
        for (int nf = 0; nf < 4; nf++) {
            int gr = growb + mt*16 + (lane >> 2);
            int gc = gcolb + nf*8 + (lane & 3)*2;
            float b0 = (gc     < SEM) ? B1v[gc]   : 0.f;
            float b1 = (gc + 1 < SEM) ? B1v[gc+1] : 0.f;
            float v0 = acc[mt][nf][0] + b0, v1 = acc[mt][nf][1] + b1;
            v0 = (gc     < SEM) ? ((v0 >= 0.f) ? v0 : 0.1f*v0) : 0.f;
            v1 = (gc + 1 < SEM) ? ((v1 >= 0.f) ? v1 : 0.1f*v1) : 0.f;
            *reinterpret_cast<float2*>(&g_H[(size_t)gr*SEMP + gc]) = make_float2(v0, v1);
            float v2 = acc[mt][nf][2] + b0, v3 = acc[mt][nf][3] + b1;
            v2 = (gc     < SEM) ? ((v2 >= 0.f) ? v2 : 0.1f*v2) : 0.f;
            v3 = (gc + 1 < SEM) ? ((v3 >= 0.f) ? v3 : 0.1f*v3) : 0.f;
            *reinterpret_cast<float2*>(&g_H[(size_t)(gr+8)*SEMP + gc]) = make_float2(v2, v3);
        }
}

// ---------------- K1: partial column sums of base_weights ----------------------------
__global__ void k1_partBW(const float* __restrict__ bw) {
    int b = blockIdx.y, s = blockIdx.x, t = threadIdx.x;
    int n0 = s * 125;
    const float* base = bw + ((size_t)(b*NBASE + n0))*FEAT;
    float a0 = 0.f, a1 = 0.f;
    #pragma unroll 4
    for (int n = 0; n < 125; n++) {
        const float* r = base + (size_t)n*FEAT;
        a0 += r[t]; a1 += r[t+256];
    }
    g_partBW[(b*64+s)*FEAT + t]       = a0;
    g_partBW[(b*64+s)*FEAT + t + 256] = a1;
}

// ---------------- K2b: partial column sums of H --------------------------------------
__global__ void k2b_partH() {
    int b = blockIdx.y, s = blockIdx.x, t = threadIdx.x;
    if (t >= SEM) return;
    int n0 = s * 125;
    const float* base = g_H + ((size_t)(b*NBASE + n0))*SEMP;
    float a0 = 0.f;
    #pragma unroll 8
    for (int n = 0; n < 125; n++) a0 += base[(size_t)n*SEMP + t];
    g_partH[(b*64+s)*SEM + t] = a0;
}

// ---------------- K3: support semantic calibration + q_tot ---------------------------
__global__ __launch_bounds__(512) void k3_qtot(
        const float* __restrict__ sf, const float* __restrict__ ss,
        const float* __restrict__ W1, const float* __restrict__ B1,
        const float* __restrict__ W2, const float* __restrict__ B2,
        const float* __restrict__ Wq, const float* __restrict__ Wqs) {
    __shared__ float s_ss[SEM], s_hid[SEM], s_cal[SEM], s_sf[FEAT];
    int idx = blockIdx.x, t = threadIdx.x;
    if (t < SEM) s_ss[t] = ss[(size_t)idx*SEM + t];
    s_sf[t] = sf[(size_t)idx*FEAT + t];
    __syncthreads();
    if (t < SEM) {
        float a0=0.f, a1=0.f, a2=0.f, a3=0.f;
        #pragma unroll 8
        for (int k = 0; k < SEM; k += 4) {
            a0 += s_ss[k  ]*W1[(size_t)(k  )*SEM + t];
            a1 += s_ss[k+1]*W1[(size_t)(k+1)*SEM + t];
            a2 += s_ss[k+2]*W1[(size_t)(k+2)*SEM + t];
            a3 += s_ss[k+3]*W1[(size_t)(k+3)*SEM + t];
        }
        float h = B1[t] + ((a0+a1)+(a2+a3));
        s_hid[t] = (h >= 0.f) ? h : 0.1f*h;
    }
    __syncthreads();
    if (t < SEM) {
        float a0=0.f, a1=0.f, a2=0.f, a3=0.f;
        #pragma unroll 8
        for (int k = 0; k < SEM; k += 4) {
            a0 += s_hid[k  ]*W2[(size_t)(k  )*SEM + t];
            a1 += s_hid[k+1]*W2[(size_t)(k+1)*SEM + t];
            a2 += s_hid[k+2]*W2[(size_t)(k+2)*SEM + t];
            a3 += s_hid[k+3]*W2[(size_t)(k+3)*SEM + t];
        }
        s_cal[t] = B2[t] + ((a0+a1)+(a2+a3));
    }
    __syncthreads();
    float q0=0.f, q1=0.f, q2=0.f, q3=0.f;
    #pragma unroll 8
    for (int k = 0; k < FEAT; k += 4) {
        q0 += s_sf[k  ]*Wq[(size_t)(k  )*FEAT + t];
        q1 += s_sf[k+1]*Wq[(size_t)(k+1)*FEAT + t];
        q2 += s_sf[k+2]*Wq[(size_t)(k+2)*FEAT + t];
        q3 += s_sf[k+3]*Wq[(size_t)(k+3)*FEAT + t];
    }
    #pragma unroll 8
    for (int k = 0; k < SEM; k += 4) {
        q0 += s_cal[k  ]*Wqs[(size_t)(k  )*FEAT + t];
        q1 += s_cal[k+1]*Wqs[(size_t)(k+1)*FEAT + t];
        q2 += s_cal[k+2]*Wqs[(size_t)(k+2)*FEAT + t];
        q3 += s_cal[k+3]*Wqs[(size_t)(k+3)*FEAT + t];
    }
    g_qtot[(size_t)idx*FEAT + t] = (q0+q1)+(q2+q3);
}

// ---------------- K4: means -> fusion gates ------------------------------------------
__global__ void k4_gates(const float* __restrict__ W2, const float* __restrict__ B2,
                         const float* __restrict__ Vw, const float* __restrict__ Vb,
                         const float* __restrict__ Sw, const float* __restrict__ Sb) {
    __shared__ float s_avg[FEAT + SEM];
    __shared__ float s_mh[SEM];
    int b = blockIdx.x, t = threadIdx.x;
    if (t < FEAT) {
        float a = 0.f;
        #pragma unroll 4
        for (int s = 0; s < 64; s++) a += g_partBW[(b*64+s)*FEAT + t];
        s_avg[t] = a * (1.f/NBASE);
    }
    if (t < SEM) {
        float a = 0.f;
        #pragma unroll 4
        for (int s = 0; s < 64; s++) a += g_partH[(b*64+s)*SEM + t];
        s_mh[t] = a * (1.f/NBASE);
    }
    __syncthreads();
    if (t < SEM) {
        float a0=0.f, a1=0.f, a2=0.f, a3=0.f;
        #pragma unroll 8
        for (int k = 0; k < SEM; k += 4) {
            a0 += s_mh[k  ]*W2[(size_t)(k  )*SEM + t];
            a1 += s_mh[k+1]*W2[(size_t)(k+1)*SEM + t];
            a2 += s_mh[k+2]*W2[(size_t)(k+2)*SEM + t];
            a3 += s_mh[k+3]*W2[(size_t)(k+3)*SEM + t];
        }
        s_avg[FEAT + t] = B2[t] + ((a0+a1)+(a2+a3));
    }
    __syncthreads();
    {
        float a0=0.f, a1=0.f, a2=0.f, a3=0.f;
        #pragma unroll 8
        for (int k = 0; k < FEAT+SEM-3; k += 4) {
            a0 += s_avg[k  ]*Vw[(size_t)(k  )*FEAT + t];
            a1 += s_avg[k+1]*Vw[(size_t)(k+1)*FEAT + t];
            a2 += s_avg[k+2]*Vw[(size_t)(k+2)*FEAT + t];
            a3 += s_avg[k+3]*Vw[(size_t)(k+3)*FEAT + t];
        }
        float g = Vb[t] + ((a0+a1)+(a2+a3));
        g_gatevis[b*FEAT + t] = 1.f + 1.f/(1.f + expf(-g));
    }
    if (t < SEM) {
        float a0=0.f, a1=0.f, a2=0.f, a3=0.f;
        #pragma unroll 8
        for (int k = 0; k < FEAT+SEM-3; k += 4) {
            a0 += s_avg[k  ]*Sw[(size_t)(k  )*SEM + t];
            a1 += s_avg[k+1]*Sw[(size_t)(k+1)*SEM + t];
            a2 += s_avg[k+2]*Sw[(size_t)(k+2)*SEM + t];
            a3 += s_avg[k+3]*Sw[(size_t)(k+3)*SEM + t];
        }
        float g = Sb[t] + ((a0+a1)+(a2+a3));
        g_gatesem[b*SEM + t] = 1.f + 1.f/(1.f + expf(-g));
    }
}

// ---------------- K4b: Wvc = w_vs @ fc_w ---------------------------------------------
__global__ __launch_bounds__(512) void k4b_wvc(const float* __restrict__ Wv,
                                               const float* __restrict__ Fc) {
    __shared__ float s_row[4][FEAT];
    int r0 = blockIdx.x*4, t = threadIdx.x;
    #pragma unroll
    for (int r = 0; r < 4; r++) s_row[r][t] = Wv[(size_t)(r0+r)*FEAT + t];
    __syncthreads();
    float a0=0.f, a1=0.f, a2=0.f, a3=0.f;
    #pragma unroll 4
    for (int k = 0; k < FEAT; k++) {
        float f = Fc[(size_t)k*FEAT + t];
        a0 += s_row[0][k]*f; a1 += s_row[1][k]*f;
        a2 += s_row[2][k]*f; a3 += s_row[3][k]*f;
    }
    g_Wvc[(size_t)(r0+0)*FEAT + t] = a0;
    g_Wvc[(size_t)(r0+1)*FEAT + t] = a1;
    g_Wvc[(size_t)(r0+2)*FEAT + t] = a2;
    g_Wvc[(size_t)(r0+3)*FEAT + t] = a3;
}

// ---------------- K5: fold W_k / gates / W2 into the query side (2-way ILP) ----------
__global__ void k5_qcat(const float* __restrict__ Wk, const float* __restrict__ Wks,
                        const float* __restrict__ W2, const float* __restrict__ B2) {
    __shared__ float s_q[FEAT];
    __shared__ float s_qsg[SEM];
    int idx = blockIdx.x, b = idx >> 4;
    int t = threadIdx.x, lane = t & 31, warp = t >> 5;
    s_q[t] = g_qtot[(size_t)idx*FEAT + t];
    __syncthreads();
    for (int i = 0; i < 32; i += 2) {
        int d0 = warp + i*16, d1 = warp + (i+1)*16;
        float acc0 = 0.f, acc1 = 0.f;
        #pragma unroll
        for (int o = lane; o < FEAT; o += 32) {
            float q = s_q[o];
            acc0 += q*Wk[(size_t)d0*FEAT + o];
            acc1 += q*Wk[(size_t)d1*FEAT + o];
        }
        for (int off = 16; off; off >>= 1) {
            acc0 += __shfl_xor_sync(0xffffffffu, acc0, off);
            acc1 += __shfl_xor_sync(0xffffffffu, acc1, off);
        }
        if (lane == 0) {
            g_Qcat[(size_t)idx*CAT + d0] = acc0 * g_gatevis[b*FEAT + d0];
            g_Qcat[(size_t)idx*CAT + d1] = acc1 * g_gatevis[b*FEAT + d1];
        }
    }
    for (int i = 0; i < 19; i += 2) {
        int s0 = warp + i*16, s1 = warp + (i+1)*16;
        bool v0 = s0 < SEM, v1 = (i+1 < 19) && (s1 < SEM);
        float acc0 = 0.f, acc1 = 0.f;
        #pragma unroll
        for (int o = lane; o < FEAT; o += 32) {
            float q = s_q[o];
            if (v0) acc0 += q*Wks[(size_t)s0*FEAT + o];
            if (v1) acc1 += q*Wks[(size_t)s1*FEAT + o];
        }
        for (int off = 16; off; off >>= 1) {
            acc0 += __shfl_xor_sync(0xffffffffu, acc0, off);
            acc1 += __shfl_xor_sync(0xffffffffu, acc1, off);
        }
        if (lane == 0) {
            if (v0) s_qsg[s0] = acc0 * g_gatesem[b*SEM + s0];
            if (v1) s_qsg[s1] = acc1 * g_gatesem[b*SEM + s1];
        }
    }
    __syncthreads();
    for (int i = 0; i < 19; i += 2) {
        int p0 = warp + i*16, p1 = warp + (i+1)*16;
        bool v0 = p0 < SEM, v1 = (i+1 < 19) && (p1 < SEM);
        float acc0 = 0.f, acc1 = 0.f;
        for (int s = lane; s < SEM; s += 32) {
            float q = s_qsg[s];
            if (v0) acc0 += q*W2[(size_t)p0*SEM + s];
            if (v1) acc1 += q*W2[(size_t)p1*SEM + s];
        }
        for (int off = 16; off; off >>= 1) {
            acc0 += __shfl_xor_sync(0xffffffffu, acc0, off);
            acc1 += __shfl_xor_sync(0xffffffffu, acc1, off);
        }
        if (lane == 0) {
            if (p0 < SEMP) g_Qcat[(size_t)idx*CAT + FEAT + p0] = v0 ? acc0 : 0.f;
            if (i+1 < 19 && p1 < SEMP) g_Qcat[(size_t)idx*CAT + FEAT + p1] = v1 ? acc1 : 0.f;
        }
    }
    if (warp == 0) {
        float acc = 0.f;
        for (int s = lane; s < SEM; s += 32) acc += s_qsg[s]*B2[s];
        for (int off = 16; off; off >>= 1) acc += __shfl_xor_sync(0xffffffffu, acc, off);
        if (lane == 0) g_c[idx] = acc;
    }
}

// ---------------- K6: scores + fused partial softmax stats ---------------------------
__global__ void k6_score(const float* __restrict__ bw, float* __restrict__ attn) {
    __shared__ __align__(16) float Qs[16][16];
    __shared__ __align__(16) float Xst[16][132];
    int b = blockIdx.y, ch = blockIdx.x;
    int n0 = ch*128;
    int nvalid = NBASE - n0; if (nvalid > 128) nvalid = 128;
    int t = threadIdx.x, lane = t & 31, warp = t >> 5;
    float acc0[4] = {0,0,0,0}, acc1[4] = {0,0,0,0};
    for (int kt = 0; kt < 51; kt++) {
        { int w = t >> 4, k = t & 15;
          Qs[w][k] = g_Qcat[(size_t)(b*NWAY + w)*CAT + kt*16 + k]; }
        #pragma unroll
        for (int i = 0; i < 2; i++) {
            int v = t + 256*i;
            int kg = v & 3, n = v >> 2;
            int kk = kt*16 + kg*4;
            float4 f = make_float4(0.f,0.f,0.f,0.f);
            if (n < nvalid) {
                if (kk < FEAT)
                    f = *reinterpret_cast<const float4*>(bw + (size_t)(b*NBASE + n0 + n)*FEAT + kk);
                else
                    f = *reinterpret_cast<const float4*>(g_H + (size_t)(b*NBASE + n0 + n)*SEMP + (kk - FEAT));
            }
            Xst[kg*4+0][n] = f.x; Xst[kg*4+1][n] = f.y; Xst[kg*4+2][n] = f.z; Xst[kg*4+3][n] = f.w;
        }
        __syncthreads();
        #pragma unroll
        for (int k = 0; k < 16; k++) {
            float q0 = Qs[warp][k];
            float q1 = Qs[warp+8][k];
            float4 x = *reinterpret_cast<const float4*>(&Xst[k][lane*4]);
            acc0[0] += q0*x.x; acc0[1] += q0*x.y; acc0[2] += q0*x.z; acc0[3] += q0*x.w;
            acc1[0] += q1*x.x; acc1[1] += q1*x.y; acc1[2] += q1*x.z; acc1[3] += q1*x.w;
        }
        __syncthreads();
    }
    float c0 = g_c[b*NWAY + warp], c1 = g_c[b*NWAY + warp + 8];
    float s0[4], s1[4];
    #pragma unroll
    for (int j = 0; j < 4; j++) {
        int n = lane*4 + j;
        bool valid = n < nvalid;
        s0[j] = valid ? (acc0[j] + c0) * INV_TEMP : -1e30f;
        s1[j] = valid ? (acc1[j] + c1) * INV_TEMP : -1e30f;
        if (valid) {
            attn[(size_t)(b*NWAY + warp    )*NBASE + n0 + n] = s0[j];
            attn[(size_t)(b*NWAY + warp + 8)*NBASE + n0 + n] = s1[j];
        }
    }
    // per-row chunk stats (max, sumexp)
    float m0 = fmaxf(fmaxf(s0[0], s0[1]), fmaxf(s0[2], s0[3]));
    float m1 = fmaxf(fmaxf(s1[0], s1[1]), fmaxf(s1[2], s1[3]));
    for (int off = 16; off; off >>= 1) {
        m0 = fmaxf(m0, __shfl_xor_sync(0xffffffffu, m0, off));
        m1 = fmaxf(m1, __shfl_xor_sync(0xffffffffu, m1, off));
    }
    float z0 = 0.f, z1 = 0.f;
    #pragma unroll
    for (int j = 0; j < 4; j++) {
        z0 += expf(s0[j] - m0);
        z1 += expf(s1[j] - m1);
    }
    for (int off = 16; off; off >>= 1) {
        z0 += __shfl_xor_sync(0xffffffffu, z0, off);
        z1 += __shfl_xor_sync(0xffffffffu, z1, off);
    }
    if (lane == 0) {
        g_pm[(b*NWAY + warp    )*NCHUNK + ch] = m0;
        g_pz[(b*NWAY + warp    )*NCHUNK + ch] = z0;
        g_pm[(b*NWAY + warp + 8)*NCHUNK + ch] = m1;
        g_pz[(b*NWAY + warp + 8)*NCHUNK + ch] = z1;
    }
}

// ---------------- K7m: merge chunk stats ---------------------------------------------
__global__ void k7m() {
    int row = blockIdx.x, lane = threadIdx.x;
    float m = -1e30f;
    for (int c = lane; c < NCHUNK; c += 32) m = fmaxf(m, g_pm[row*NCHUNK + c]);
    for (int off = 16; off; off >>= 1) m = fmaxf(m, __shfl_xor_sync(0xffffffffu, m, off));
    float z = 0.f;
    for (int c = lane; c < NCHUNK; c += 32)
        z += expf(g_pm[row*NCHUNK + c] - m) * g_pz[row*NCHUNK + c];
    for (int off = 16; off; off >>= 1) z += __shfl_xor_sync(0xffffffffu, z, off);
    if (lane == 0) { g_m[row] = m; g_Z[row] = z; }
}

// ---------------- K8: partial attn @ base_weights (f32x2) ----------------------------
__global__ __launch_bounds__(256) void k8_part(const float* __restrict__ bw,
                                               const float* __restrict__ attn) {
    __shared__ unsigned long long p64[NWAY*250];
    int b = blockIdx.y, c = blockIdx.x, t = threadIdx.x;
    int n0 = c*250;
    for (int v = t; v < NWAY*250; v += 256) {
        int w = v/250, n = v - w*250;
        float s = attn[(size_t)(b*NWAY+w)*NBASE + n0 + n];
        float e = expf(s - g_m[b*NWAY+w]);
        p64[v] = f2pk(e, e);
    }
    __syncthreads();
    unsigned long long acc[NWAY];
    #pragma unroll
    for (int w = 0; w < NWAY; w++) acc[w] = 0ULL;
    const float* base = bw + (size_t)(b*NBASE + n0)*FEAT + 2*t;
    for (int n = 0; n < 250; n++) {
        unsigned long long x = *reinterpret_cast<const unsigned long long*>(base + (size_t)n*FEAT);
        #pragma unroll
        for (int w = 0; w < NWAY; w++)
            acc[w] = f2fma(p64[w*250 + n], x, acc[w]);
    }
    #pragma unroll
    for (int w = 0; w < NWAY; w++) {
        size_t o = (size_t)((b*32 + c)*NWAY + w)*FEAT;
        float lo, hi;
        f2up(acc[w], lo, hi);
        *reinterpret_cast<float2*>(&g_part[o + 2*t]) = make_float2(lo, hi);
    }
}

// ---------------- K9: reduce partials, @Wvc, +residual -------------------------------
__global__ void k9_out(const float* __restrict__ sf, float* __restrict__ out) {
    __shared__ float s_s[FEAT];
    int idx = blockIdx.x, t = threadIdx.x;
    int b = idx >> 4, w = idx & 15;
    float acc = 0.f;
    #pragma unroll 4
    for (int c = 0; c < 32; c++) acc += g_part[(size_t)((b*32+c)*NWAY + w)*FEAT + t];
    s_s[t] = acc / g_Z[idx];
    __syncthreads();
    float v = sf[(size_t)idx*FEAT + t];
    float a0=0.f, a1=0.f, a2=0.f, a3=0.f;
    #pragma unroll 8
    for (int d = 0; d < FEAT; d += 4) {
        a0 += s_s[d  ]*g_Wvc[(size_t)(d  )*FEAT + t];
        a1 += s_s[d+1]*g_Wvc[(size_t)(d+1)*FEAT + t];
        a2 += s_s[d+2]*g_Wvc[(size_t)(d+2)*FEAT + t];
        a3 += s_s[d+3]*g_Wvc[(size_t)(d+3)*FEAT + t];
    }
    out[(size_t)idx*FEAT + t] = v + ((a0+a1)+(a2+a3));
}

// ---------------- launch --------------------------------------------------------------
extern "C" void kernel_launch(void* const* d_in, const int* in_sizes, int n_in,
                              void* d_out, int out_size) {
    const float* sf  = (const float*)d_in[0];
    const float* bw  = (const float*)d_in[1];
    const float* ss  = (const float*)d_in[2];
    const float* bs  = (const float*)d_in[3];
    const float* w1  = (const float*)d_in[4];
    const float* b1  = (const float*)d_in[5];
    const float* w2  = (const float*)d_in[6];
    const float* b2  = (const float*)d_in[7];
    const float* vw  = (const float*)d_in[8];
    const float* vb  = (const float*)d_in[9];
    const float* swf = (const float*)d_in[10];
    const float* sb  = (const float*)d_in[11];
    const float* wq  = (const float*)d_in[12];
    const float* wk  = (const float*)d_in[13];
    const float* wv  = (const float*)d_in[14];
    const float* wqs = (const float*)d_in[15];
    const float* wks = (const float*)d_in[16];
    const float* fc  = (const float*)d_in[17];
    float* out  = (float*)d_out;
    float* attn = out + (size_t)NROW*FEAT;

    cudaFuncSetAttribute(k2t, cudaFuncAttributeMaxDynamicSharedMemorySize, 49152);

    k2w<<<(304*304 + 255)/256, 256>>>(w1);
    k1_partBW<<<dim3(64, NB), 256>>>(bw);
    k3_qtot<<<NROW, 512>>>(sf, ss, w1, b1, w2, b2, wq, wqs);
    k2t<<<dim3(3, 500), 512, 49152>>>(bs, b1);         // 4th launch -> profiled
    k2b_partH<<<dim3(64, NB), 320>>>();
    k4_gates<<<NB, 512>>>(w2, b2, vw, vb, swf, sb);
    k4b_wvc<<<128, 512>>>(wv, fc);
    k5_qcat<<<NROW, 512>>>(wk, wks, w2, b2);
    k6_score<<<dim3(NCHUNK, NB), 256>>>(bw, attn);
    k7m<<<NROW, 32>>>();
    k8_part<<<dim3(32, NB), 256>>>(bw, attn);
    k9_out<<<NROW, 512>>>(sf, out);
}